// round 1
// baseline (speedup 1.0000x reference)
#include <cuda_runtime.h>
#include <cuda_bf16.h>
#include <math.h>

#define NPROP 2000
#define NGT   100
#define TR    200
#define PM    66      // POS_MAX = int(200*0.33)
#define HH    512
#define WW    512
#define MS    28

// inter-kernel state (no allocs allowed -> device globals)
__device__ int      g_npos[2];
__device__ int      g_posidx[2 * PM];
__device__ int      g_posg[2 * PM];
__device__ unsigned g_maskflags;

// ---------------------------------------------------------------------------
// Kernel 0: probe gt_masks dtype from bit patterns of 0/1-valued data.
// flags: 1=u8, 2=f32 (or ambiguous), 4=bf16. Deterministic overwrite.
// ---------------------------------------------------------------------------
__global__ void detect_mask_dtype(const unsigned* __restrict__ w) {
    __shared__ unsigned fl;
    if (threadIdx.x == 0) fl = 0u;
    __syncthreads();
    unsigned local = 0u;
    for (int i = threadIdx.x; i < 2048; i += blockDim.x) {
        unsigned v = w[i];
        if (v == 0u || v == 1u) continue;                       // i32-compatible
        else if (v == 0x3F803F80u || v == 0x00003F80u) local |= 4u;  // bf16 pair
        else if (v == 0x3F800000u)                     local |= 2u;  // f32 1.0
        else if ((v & ~0x01010101u) == 0u)             local |= 1u;  // u8 bytes
    }
    atomicOr(&fl, local);
    __syncthreads();
    if (threadIdx.x == 0) g_maskflags = fl;
}

// ---------------------------------------------------------------------------
// Kernel 1: one block per batch. IoU, pos/neg classification, stable
// compaction via ballot+popc, subsample counts, rois/class/deltas outputs.
// ---------------------------------------------------------------------------
__global__ __launch_bounds__(1024) void dtl_main(
    const float* __restrict__ props,
    const int*   __restrict__ cls,
    const float* __restrict__ gtb,
    float*       __restrict__ out)
{
    const int b   = blockIdx.x;
    const int tid = threadIdx.x;

    __shared__ float         s_gt[NGT][4];
    __shared__ int           s_cls[NGT];
    __shared__ unsigned char s_fg[NGT], s_crowd[NGT];
    __shared__ unsigned      s_pb[63], s_nb[63];
    __shared__ int           s_pbase[64], s_nbase[64];
    __shared__ int           s_pord[PM];
    __shared__ int           s_nord[TR];
    __shared__ unsigned char s_assign[2048];
    __shared__ int           s_Np, s_Nn;

    const float* P = props + (size_t)b * NPROP * 4;
    const float* G = gtb   + (size_t)b * NGT * 4;
    const int*   C = cls   + (size_t)b * NGT;

    if (tid < NGT) {
        float g0 = G[tid*4+0], g1 = G[tid*4+1], g2 = G[tid*4+2], g3 = G[tid*4+3];
        s_gt[tid][0] = g0; s_gt[tid][1] = g1; s_gt[tid][2] = g2; s_gt[tid][3] = g3;
        bool vg = (fabsf(g0)+fabsf(g1)+fabsf(g2)+fabsf(g3)) > 0.0f;
        int c = C[tid];
        s_cls[tid]   = c;
        s_fg[tid]    = (vg && c > 0) ? 1 : 0;
        s_crowd[tid] = (vg && c < 0) ? 1 : 0;
    }
    __syncthreads();

    bool posb[2], negb[2];
    #pragma unroll
    for (int ch = 0; ch < 2; ch++) {
        int n = tid + ch * 1024;
        bool pb = false, nb = false;
        unsigned char asg = 0;
        if (n < NPROP) {
            float p0 = P[n*4+0], p1 = P[n*4+1], p2 = P[n*4+2], p3 = P[n*4+3];
            bool vp = (fabsf(p0)+fabsf(p1)+fabsf(p2)+fabsf(p3)) > 0.0f;
            float a1 = (p2 - p0) * (p3 - p1);
            float fgmax = 0.0f, crmax = 0.0f, best = -1e30f;
            int bi = 0;
            for (int g = 0; g < NGT; g++) {
                float q0 = s_gt[g][0], q1 = s_gt[g][1], q2 = s_gt[g][2], q3 = s_gt[g][3];
                float y1 = fmaxf(p0, q0);
                float x1 = fmaxf(p1, q1);
                float y2 = fminf(p2, q2);
                float x2 = fminf(p3, q3);
                float inter = fmaxf(x2 - x1, 0.0f) * fmaxf(y2 - y1, 0.0f);
                float a2 = (q2 - q0) * (q3 - q1);
                float un = a1 + a2 - inter;
                float iou = (un > 0.0f) ? (inter / un) : 0.0f;
                if (!vp) iou = 0.0f;
                if (s_crowd[g] && iou > crmax) crmax = iou;
                float fv = s_fg[g] ? iou : 0.0f;
                if (fv > fgmax) fgmax = fv;
                float av = s_fg[g] ? iou : -1.0f;
                if (av > best) { best = av; bi = g; }
            }
            pb = (fgmax >= 0.5f) && vp;
            nb = (fgmax <  0.5f) && (crmax < 0.001f) && vp;
            asg = (unsigned char)bi;
        }
        posb[ch] = pb; negb[ch] = nb;
        s_assign[n] = asg;
        unsigned pm = __ballot_sync(0xffffffffu, pb);
        unsigned nm = __ballot_sync(0xffffffffu, nb);
        int w = n >> 5;
        if ((tid & 31) == 0 && w < 63) { s_pb[w] = pm; s_nb[w] = nm; }
    }
    __syncthreads();

    if (tid == 0) {
        int rp = 0, rn = 0;
        for (int w = 0; w < 63; w++) {
            s_pbase[w] = rp; rp += __popc(s_pb[w]);
            s_nbase[w] = rn; rn += __popc(s_nb[w]);
        }
        s_pbase[63] = rp; s_nbase[63] = rn;
        int Np = min(rp, PM);
        const float R = (float)(1.0 / 0.33);             // same f32 constant as XLA
        int want = (int)floorf(R * (float)Np) - Np;
        int Nn = min(want, rn);
        Nn = max(Nn, 0);
        Nn = min(Nn, TR - Np);
        s_Np = Np; s_Nn = Nn;
        g_npos[b] = Np;
    }
    __syncthreads();

    #pragma unroll
    for (int ch = 0; ch < 2; ch++) {
        int n = tid + ch * 1024;
        int w = n >> 5, l = n & 31;
        if (w < 63) {
            unsigned lm = (1u << l) - 1u;
            if (posb[ch]) {
                int r = s_pbase[w] + __popc(s_pb[w] & lm);
                if (r < PM) s_pord[r] = n;
            }
            if (negb[ch]) {
                int r = s_nbase[w] + __popc(s_nb[w] & lm);
                if (r < TR) s_nord[r] = n;
            }
        }
    }
    __syncthreads();

    const int Np = s_Np, Nn = s_Nn;
    if (tid < TR) {
        const int j = tid;
        float* ro = out + (size_t)(b * TR + j) * 4;
        float* cl = out + 1600 + (size_t)(b * TR + j);
        float* de = out + 2000 + (size_t)(b * TR + j) * 4;
        if (j < Np) {
            int n = s_pord[j];
            int g = s_assign[n];
            float p0 = P[n*4+0], p1 = P[n*4+1], p2 = P[n*4+2], p3 = P[n*4+3];
            ro[0] = p0; ro[1] = p1; ro[2] = p2; ro[3] = p3;
            cl[0] = (float)s_cls[g];
            float h  = p2 - p0, w2 = p3 - p1;
            float cy = p0 + 0.5f * h, cx = p1 + 0.5f * w2;
            float g0 = s_gt[g][0], g1 = s_gt[g][1], g2 = s_gt[g][2], g3 = s_gt[g][3];
            float gh = g2 - g0, gw = g3 - g1;
            float gcy = g0 + 0.5f * gh, gcx = g1 + 0.5f * gw;
            de[0] = ((gcy - cy) / h)  / 0.1f;
            de[1] = ((gcx - cx) / w2) / 0.1f;
            de[2] = logf(gh / h)  / 0.2f;
            de[3] = logf(gw / w2) / 0.2f;
            if (j < PM) { g_posidx[b * PM + j] = n; g_posg[b * PM + j] = g; }
        } else if (j < Np + Nn) {
            int n = s_nord[j - Np];
            ro[0] = P[n*4+0]; ro[1] = P[n*4+1]; ro[2] = P[n*4+2]; ro[3] = P[n*4+3];
            cl[0] = 0.0f;
            de[0] = de[1] = de[2] = de[3] = 0.0f;
        } else {
            ro[0] = ro[1] = ro[2] = ro[3] = 0.0f;
            cl[0] = 0.0f;
            de[0] = de[1] = de[2] = de[3] = 0.0f;
        }
    }
}

// ---------------------------------------------------------------------------
// Kernel 2: one block per (batch, roi-row). 28x28 bilinear crop-resize from
// gt_masks[b, :, :, g] for positive rows, zeros otherwise.
// ---------------------------------------------------------------------------
__global__ void dtl_masks(const float* __restrict__ props,
                          const void*  __restrict__ masks,
                          float*       __restrict__ out)
{
    const int bj = blockIdx.x;
    const int b = bj / TR, j = bj % TR;
    float* om = out + 3600 + (size_t)(b * TR + j) * (MS * MS);
    const int Np = g_npos[b];
    if (j >= Np) {
        for (int p = threadIdx.x; p < MS * MS; p += blockDim.x) om[p] = 0.0f;
        return;
    }
    const int n = g_posidx[b * PM + j];
    const int g = g_posg[b * PM + j];
    const float* P = props + ((size_t)b * NPROP + n) * 4;
    const float y1 = P[0], x1 = P[1], y2 = P[2], x2 = P[3];
    const float sy = ((y2 - y1) * 511.0f) / 27.0f;
    const float sx = ((x2 - x1) * 511.0f) / 27.0f;
    const unsigned mode = g_maskflags;
    const size_t mb = (size_t)b * HH * WW * NGT;

    for (int p = threadIdx.x; p < MS * MS; p += blockDim.x) {
        const int i = p / MS, k = p % MS;
        const float ys = y1 * 511.0f + (float)i * sy;
        const float xs = x1 * 511.0f + (float)k * sx;
        const float y0f = floorf(ys), x0f = floorf(xs);
        const float wy = ys - y0f, wx = xs - x0f;
        const int y0i = (int)fminf(fmaxf(y0f,        0.0f), 511.0f);
        const int y1i = (int)fminf(fmaxf(y0f + 1.0f, 0.0f), 511.0f);
        const int x0i = (int)fminf(fmaxf(x0f,        0.0f), 511.0f);
        const int x1i = (int)fminf(fmaxf(x0f + 1.0f, 0.0f), 511.0f);
        const size_t i00 = mb + ((size_t)(y0i * WW + x0i)) * NGT + g;
        const size_t i01 = mb + ((size_t)(y0i * WW + x1i)) * NGT + g;
        const size_t i10 = mb + ((size_t)(y1i * WW + x0i)) * NGT + g;
        const size_t i11 = mb + ((size_t)(y1i * WW + x1i)) * NGT + g;
        float v00, v01, v10, v11;
        if (mode & 4u) {
            const __nv_bfloat16* m = (const __nv_bfloat16*)masks;
            v00 = __bfloat162float(m[i00]); v01 = __bfloat162float(m[i01]);
            v10 = __bfloat162float(m[i10]); v11 = __bfloat162float(m[i11]);
        } else if (mode & 2u) {
            const float* m = (const float*)masks;
            v00 = m[i00]; v01 = m[i01]; v10 = m[i10]; v11 = m[i11];
        } else if (mode & 1u) {
            const unsigned char* m = (const unsigned char*)masks;
            v00 = (float)m[i00]; v01 = (float)m[i01];
            v10 = (float)m[i10]; v11 = (float)m[i11];
        } else {
            const int* m = (const int*)masks;
            v00 = (float)m[i00]; v01 = (float)m[i01];
            v10 = (float)m[i10]; v11 = (float)m[i11];
        }
        float val = (v00 * (1.0f - wx) + v01 * wx) * (1.0f - wy)
                  + (v10 * (1.0f - wx) + v11 * wx) * wy;
        const bool ok = (ys >= 0.0f) && (ys <= 511.0f) && (xs >= 0.0f) && (xs <= 511.0f);
        val = ok ? val : 0.0f;
        om[p] = rintf(val);   // round-half-even == jnp.round
    }
}

// ---------------------------------------------------------------------------
extern "C" void kernel_launch(void* const* d_in, const int* in_sizes, int n_in,
                              void* d_out, int out_size)
{
    const float* props = (const float*)d_in[0];
    const int*   cls   = (const int*)  d_in[1];
    const float* gtb   = (const float*)d_in[2];
    const void*  masks = d_in[3];
    float* out = (float*)d_out;

    detect_mask_dtype<<<1, 256>>>((const unsigned*)masks);
    dtl_main<<<2, 1024>>>(props, cls, gtb, out);
    dtl_masks<<<2 * TR, 256>>>(props, masks, out);
}

// round 2
// speedup vs baseline: 2.2333x; 2.2333x over previous
#include <cuda_runtime.h>
#include <cuda_bf16.h>
#include <math.h>

#define NPROP 2000
#define NGT   100
#define TR    200
#define PM    66      // POS_MAX = int(200*0.33)
#define HH    512
#define WW    512
#define MS    28
#define BLKS_PER_B 16      // classify blocks per batch (16 x 128 = 2048 >= 2000)

// inter-kernel / inter-block state (no allocs allowed -> device globals)
__device__ int           g_npos[2];
__device__ int           g_posidx[2 * PM];
__device__ int           g_posg[2 * PM];
__device__ unsigned      g_maskflags;          // OR-accumulated: idempotent across replays
__device__ unsigned      g_pb[2][64];
__device__ unsigned      g_nb[2][64];
__device__ unsigned char g_asg[2][2048];
__device__ int           g_done[2];            // reset to 0 by finalizing block each launch

// ---------------------------------------------------------------------------
// Kernel A: classify (32 blocks x 128 thr) + last-block-per-batch finalize.
// Block 0 additionally probes the gt_masks dtype (overlapped, idempotent).
// ---------------------------------------------------------------------------
__global__ __launch_bounds__(128) void dtl_classify(
    const float* __restrict__ props,
    const int*   __restrict__ cls,
    const float* __restrict__ gtb,
    const unsigned* __restrict__ maskw,
    float*       __restrict__ out)
{
    const int tid = threadIdx.x;
    const int b   = blockIdx.x >> 4;
    const int blk = blockIdx.x & (BLKS_PER_B - 1);
    const int n   = blk * 128 + tid;

    __shared__ float         s_gt[NGT][4];
    __shared__ int           s_cls[NGT];
    __shared__ unsigned char s_fg[NGT], s_crowd[NGT];

    const float* P = props + (size_t)b * NPROP * 4;
    const float* G = gtb   + (size_t)b * NGT * 4;
    const int*   C = cls   + (size_t)b * NGT;

    if (tid < NGT) {
        float g0 = G[tid*4+0], g1 = G[tid*4+1], g2 = G[tid*4+2], g3 = G[tid*4+3];
        s_gt[tid][0] = g0; s_gt[tid][1] = g1; s_gt[tid][2] = g2; s_gt[tid][3] = g3;
        bool vg = (fabsf(g0)+fabsf(g1)+fabsf(g2)+fabsf(g3)) > 0.0f;
        int c = C[tid];
        s_cls[tid]   = c;
        s_fg[tid]    = (vg && c > 0) ? 1 : 0;
        s_crowd[tid] = (vg && c < 0) ? 1 : 0;
    }

    // dtype probe (block 0 only): 128 threads x 16 words = 2048 words
    if (blockIdx.x == 0) {
        unsigned local = 0u;
        #pragma unroll
        for (int it = 0; it < 16; it++) {
            unsigned v = maskw[tid + it * 128];
            if (v == 0u || v == 1u) continue;                        // i32-compatible
            else if (v == 0x3F803F80u || v == 0x00003F80u) local |= 4u;  // bf16 pair
            else if (v == 0x3F800000u)                     local |= 2u;  // f32 1.0
            else if ((v & ~0x01010101u) == 0u)             local |= 1u;  // u8 bytes
        }
        local = __reduce_or_sync(0xffffffffu, local);
        if ((tid & 31) == 0 && local) atomicOr(&g_maskflags, local);
    }
    __syncthreads();

    // ---- classify one proposal per thread ----
    bool pb = false, nb = false;
    unsigned char asg = 0;
    if (n < NPROP) {
        float p0 = P[n*4+0], p1 = P[n*4+1], p2 = P[n*4+2], p3 = P[n*4+3];
        bool vp = (fabsf(p0)+fabsf(p1)+fabsf(p2)+fabsf(p3)) > 0.0f;
        float a1 = (p2 - p0) * (p3 - p1);
        float fgmax = 0.0f, crmax = 0.0f, best = -1e30f;
        int bi = 0;
        #pragma unroll 4
        for (int g = 0; g < NGT; g++) {
            float q0 = s_gt[g][0], q1 = s_gt[g][1], q2 = s_gt[g][2], q3 = s_gt[g][3];
            float y1 = fmaxf(p0, q0);
            float x1 = fmaxf(p1, q1);
            float y2 = fminf(p2, q2);
            float x2 = fminf(p3, q3);
            float inter = fmaxf(x2 - x1, 0.0f) * fmaxf(y2 - y1, 0.0f);
            float a2 = (q2 - q0) * (q3 - q1);
            float un = a1 + a2 - inter;
            float iou = (un > 0.0f) ? (inter / un) : 0.0f;
            if (!vp) iou = 0.0f;
            if (s_crowd[g] && iou > crmax) crmax = iou;
            float fv = s_fg[g] ? iou : 0.0f;
            if (fv > fgmax) fgmax = fv;
            float av = s_fg[g] ? iou : -1.0f;
            if (av > best) { best = av; bi = g; }
        }
        pb = (fgmax >= 0.5f) && vp;
        nb = (fgmax <  0.5f) && (crmax < 0.001f) && vp;
        asg = (unsigned char)bi;
    }
    unsigned pm = __ballot_sync(0xffffffffu, pb);
    unsigned nm = __ballot_sync(0xffffffffu, nb);
    const int w = n >> 5;
    if ((tid & 31) == 0) { g_pb[b][w] = pm; g_nb[b][w] = nm; }
    if (n < 2048) g_asg[b][n] = asg;

    // ---- last block per batch finalizes ----
    __shared__ int s_isLast;
    __syncthreads();
    if (tid == 0) {
        __threadfence();
        int old = atomicAdd(&g_done[b], 1);
        s_isLast = (old == BLKS_PER_B - 1) ? 1 : 0;
    }
    __syncthreads();
    if (!s_isLast) return;
    __threadfence();

    __shared__ unsigned s_pw[64], s_nw[64];
    __shared__ int      s_pbase[64], s_nbase[64];
    __shared__ int      s_pord[PM];
    __shared__ int      s_nord[TR];
    __shared__ int      s_Np, s_Nn;

    if (tid < 63) { s_pw[tid] = g_pb[b][tid]; s_nw[tid] = g_nb[b][tid]; }
    __syncthreads();

    if (tid == 0) {
        int rp = 0, rn = 0;
        for (int v = 0; v < 63; v++) {
            s_pbase[v] = rp; rp += __popc(s_pw[v]);
            s_nbase[v] = rn; rn += __popc(s_nw[v]);
        }
        int Np = min(rp, PM);
        const float R = (float)(1.0 / 0.33);
        int want = (int)floorf(R * (float)Np) - Np;
        int Nn = min(want, rn);
        Nn = max(Nn, 0);
        Nn = min(Nn, TR - Np);
        s_Np = Np; s_Nn = Nn;
        g_npos[b] = Np;
        g_done[b] = 0;                    // reset for next graph replay
    }
    __syncthreads();

    if (tid < 63) {
        unsigned pw = s_pw[tid], nw = s_nw[tid];
        int base = s_pbase[tid];
        while (pw) {
            int l = __ffs(pw) - 1; pw &= pw - 1;
            if (base < PM) s_pord[base] = (tid << 5) + l;
            base++;
        }
        base = s_nbase[tid];
        while (nw) {
            int l = __ffs(nw) - 1; nw &= nw - 1;
            if (base < TR) s_nord[base] = (tid << 5) + l;
            base++;
        }
    }
    __syncthreads();

    const int Np = s_Np, Nn = s_Nn;
    for (int j = tid; j < TR; j += 128) {
        float* ro = out + (size_t)(b * TR + j) * 4;
        float* cl = out + 1600 + (size_t)(b * TR + j);
        float* de = out + 2000 + (size_t)(b * TR + j) * 4;
        if (j < Np) {
            int nn = s_pord[j];
            int g  = g_asg[b][nn];
            float p0 = P[nn*4+0], p1 = P[nn*4+1], p2 = P[nn*4+2], p3 = P[nn*4+3];
            ro[0] = p0; ro[1] = p1; ro[2] = p2; ro[3] = p3;
            cl[0] = (float)s_cls[g];
            float h  = p2 - p0, w2 = p3 - p1;
            float cy = p0 + 0.5f * h, cx = p1 + 0.5f * w2;
            float g0 = s_gt[g][0], g1 = s_gt[g][1], g2 = s_gt[g][2], g3 = s_gt[g][3];
            float gh = g2 - g0, gw = g3 - g1;
            float gcy = g0 + 0.5f * gh, gcx = g1 + 0.5f * gw;
            de[0] = ((gcy - cy) / h)  / 0.1f;
            de[1] = ((gcx - cx) / w2) / 0.1f;
            de[2] = logf(gh / h)  / 0.2f;
            de[3] = logf(gw / w2) / 0.2f;
            if (j < PM) { g_posidx[b * PM + j] = nn; g_posg[b * PM + j] = g; }
        } else if (j < Np + Nn) {
            int nn = s_nord[j - Np];
            ro[0] = P[nn*4+0]; ro[1] = P[nn*4+1]; ro[2] = P[nn*4+2]; ro[3] = P[nn*4+3];
            cl[0] = 0.0f;
            de[0] = de[1] = de[2] = de[3] = 0.0f;
        } else {
            ro[0] = ro[1] = ro[2] = ro[3] = 0.0f;
            cl[0] = 0.0f;
            de[0] = de[1] = de[2] = de[3] = 0.0f;
        }
    }
}

// ---------------------------------------------------------------------------
// Kernel B: one block per (batch, roi-row). 28x28 bilinear crop-resize.
// ---------------------------------------------------------------------------
__global__ __launch_bounds__(256) void dtl_masks(
    const float* __restrict__ props,
    const void*  __restrict__ masks,
    float*       __restrict__ out)
{
    const int bj = blockIdx.x;
    const int b = bj / TR, j = bj % TR;
    float* om = out + 3600 + (size_t)(b * TR + j) * (MS * MS);
    const int Np = g_npos[b];
    if (j >= Np) {
        for (int p = threadIdx.x; p < MS * MS; p += blockDim.x) om[p] = 0.0f;
        return;
    }
    const int n = g_posidx[b * PM + j];
    const int g = g_posg[b * PM + j];
    const float* P = props + ((size_t)b * NPROP + n) * 4;
    const float y1 = P[0], x1 = P[1], y2 = P[2], x2 = P[3];
    const float sy = ((y2 - y1) * 511.0f) / 27.0f;
    const float sx = ((x2 - x1) * 511.0f) / 27.0f;
    const unsigned mode = g_maskflags;
    const size_t mb = (size_t)b * HH * WW * NGT;

    for (int p = threadIdx.x; p < MS * MS; p += blockDim.x) {
        const int i = p / MS, k = p % MS;
        const float ys = y1 * 511.0f + (float)i * sy;
        const float xs = x1 * 511.0f + (float)k * sx;
        const float y0f = floorf(ys), x0f = floorf(xs);
        const float wy = ys - y0f, wx = xs - x0f;
        const int y0i = (int)fminf(fmaxf(y0f,        0.0f), 511.0f);
        const int y1i = (int)fminf(fmaxf(y0f + 1.0f, 0.0f), 511.0f);
        const int x0i = (int)fminf(fmaxf(x0f,        0.0f), 511.0f);
        const int x1i = (int)fminf(fmaxf(x0f + 1.0f, 0.0f), 511.0f);
        const size_t i00 = mb + ((size_t)(y0i * WW + x0i)) * NGT + g;
        const size_t i01 = mb + ((size_t)(y0i * WW + x1i)) * NGT + g;
        const size_t i10 = mb + ((size_t)(y1i * WW + x0i)) * NGT + g;
        const size_t i11 = mb + ((size_t)(y1i * WW + x1i)) * NGT + g;
        float v00, v01, v10, v11;
        if (mode & 4u) {
            const __nv_bfloat16* m = (const __nv_bfloat16*)masks;
            v00 = __bfloat162float(m[i00]); v01 = __bfloat162float(m[i01]);
            v10 = __bfloat162float(m[i10]); v11 = __bfloat162float(m[i11]);
        } else if (mode & 2u) {
            const float* m = (const float*)masks;
            v00 = m[i00]; v01 = m[i01]; v10 = m[i10]; v11 = m[i11];
        } else if (mode & 1u) {
            const unsigned char* m = (const unsigned char*)masks;
            v00 = (float)m[i00]; v01 = (float)m[i01];
            v10 = (float)m[i10]; v11 = (float)m[i11];
        } else {
            const int* m = (const int*)masks;
            v00 = (float)m[i00]; v01 = (float)m[i01];
            v10 = (float)m[i10]; v11 = (float)m[i11];
        }
        float val = (v00 * (1.0f - wx) + v01 * wx) * (1.0f - wy)
                  + (v10 * (1.0f - wx) + v11 * wx) * wy;
        const bool ok = (ys >= 0.0f) && (ys <= 511.0f) && (xs >= 0.0f) && (xs <= 511.0f);
        val = ok ? val : 0.0f;
        om[p] = rintf(val);   // round-half-even == jnp.round
    }
}

// ---------------------------------------------------------------------------
extern "C" void kernel_launch(void* const* d_in, const int* in_sizes, int n_in,
                              void* d_out, int out_size)
{
    const float* props = (const float*)d_in[0];
    const int*   cls   = (const int*)  d_in[1];
    const float* gtb   = (const float*)d_in[2];
    const void*  masks = d_in[3];
    float* out = (float*)d_out;

    dtl_classify<<<2 * BLKS_PER_B, 128>>>(props, cls, gtb, (const unsigned*)masks, out);
    dtl_masks<<<2 * TR, 256>>>(props, masks, out);
}

// round 3
// speedup vs baseline: 2.3549x; 1.0545x over previous
#include <cuda_runtime.h>
#include <cuda_bf16.h>
#include <math.h>

#define NPROP 2000
#define NGT   100
#define TR    200
#define PM    66      // POS_MAX = int(200*0.33)
#define HH    512
#define WW    512
#define MS    28
#define CBLK_PER_B 8          // classify blocks per batch (8 x 256 = 2048 >= 2000)
#define NCBLK (2 * CBLK_PER_B)
#define NMBLK (2 * TR)

// inter-block state (no allocs allowed -> device globals)
__device__ int           g_npos[2];
__device__ int           g_posidx[2 * PM];
__device__ int           g_posg[2 * PM];
__device__ unsigned      g_maskflags;          // OR-accumulated: idempotent across replays
__device__ unsigned      g_pb[2][64];
__device__ unsigned      g_nb[2][64];
__device__ unsigned char g_asg[2][2048];
__device__ int           g_done[2];            // classify-done counter (reset by finalizer)
__device__ int           g_ready[2];           // set by finalizer, reset by last mask block
__device__ int           g_mdone[2];           // mask-done counter (reset by last mask block)

// ---------------------------------------------------------------------------
// Fused kernel. Blocks [0, NCBLK): classification + per-batch finalize.
// Blocks [NCBLK, NCBLK+NMBLK): one ROI-row mask each; zero output eagerly,
// spin on g_ready[b], then bilinear crop-resize for positive rows.
// ---------------------------------------------------------------------------
__global__ __launch_bounds__(256) void dtl_fused(
    const float* __restrict__ props,
    const int*   __restrict__ cls,
    const float* __restrict__ gtb,
    const void*  __restrict__ masks,
    float*       __restrict__ out)
{
    const int tid = threadIdx.x;

    // =================== MASK BLOCKS ===================
    if (blockIdx.x >= NCBLK) {
        const int bj = blockIdx.x - NCBLK;
        const int b = bj / TR, j = bj % TR;
        float* om = out + 3600 + (size_t)(b * TR + j) * (MS * MS);

        // eager zero (overlaps with classification)
        #pragma unroll
        for (int p = tid; p < MS * MS; p += 256) om[p] = 0.0f;

        // wait for classification of this batch
        __shared__ int s_go;
        if (tid == 0) {
            while (*((volatile int*)&g_ready[b]) == 0) __nanosleep(64);
            s_go = 1;
        }
        __syncthreads();
        __threadfence();
        (void)s_go;

        const int Np = *((volatile int*)&g_npos[b]);
        if (j < Np) {
            const int n = g_posidx[b * PM + j];
            const int g = g_posg[b * PM + j];
            const float* P = props + ((size_t)b * NPROP + n) * 4;
            const float y1 = P[0], x1 = P[1], y2 = P[2], x2 = P[3];
            const float sy = ((y2 - y1) * 511.0f) / 27.0f;
            const float sx = ((x2 - x1) * 511.0f) / 27.0f;
            const unsigned mode = g_maskflags;
            const size_t mb = (size_t)b * HH * WW * NGT;

            for (int p = tid; p < MS * MS; p += 256) {
                const int i = p / MS, k = p % MS;
                const float ys = y1 * 511.0f + (float)i * sy;
                const float xs = x1 * 511.0f + (float)k * sx;
                const float y0f = floorf(ys), x0f = floorf(xs);
                const float wy = ys - y0f, wx = xs - x0f;
                const int y0i = (int)fminf(fmaxf(y0f,        0.0f), 511.0f);
                const int y1i = (int)fminf(fmaxf(y0f + 1.0f, 0.0f), 511.0f);
                const int x0i = (int)fminf(fmaxf(x0f,        0.0f), 511.0f);
                const int x1i = (int)fminf(fmaxf(x0f + 1.0f, 0.0f), 511.0f);
                const size_t i00 = mb + ((size_t)(y0i * WW + x0i)) * NGT + g;
                const size_t i01 = mb + ((size_t)(y0i * WW + x1i)) * NGT + g;
                const size_t i10 = mb + ((size_t)(y1i * WW + x0i)) * NGT + g;
                const size_t i11 = mb + ((size_t)(y1i * WW + x1i)) * NGT + g;
                float v00, v01, v10, v11;
                if (mode & 4u) {
                    const __nv_bfloat16* m = (const __nv_bfloat16*)masks;
                    v00 = __bfloat162float(m[i00]); v01 = __bfloat162float(m[i01]);
                    v10 = __bfloat162float(m[i10]); v11 = __bfloat162float(m[i11]);
                } else if (mode & 2u) {
                    const float* m = (const float*)masks;
                    v00 = m[i00]; v01 = m[i01]; v10 = m[i10]; v11 = m[i11];
                } else if (mode & 1u) {
                    const unsigned char* m = (const unsigned char*)masks;
                    v00 = (float)m[i00]; v01 = (float)m[i01];
                    v10 = (float)m[i10]; v11 = (float)m[i11];
                } else {
                    const int* m = (const int*)masks;
                    v00 = (float)m[i00]; v01 = (float)m[i01];
                    v10 = (float)m[i10]; v11 = (float)m[i11];
                }
                float val = (v00 * (1.0f - wx) + v01 * wx) * (1.0f - wy)
                          + (v10 * (1.0f - wx) + v11 * wx) * wy;
                const bool ok = (ys >= 0.0f) && (ys <= 511.0f) && (xs >= 0.0f) && (xs <= 511.0f);
                val = ok ? val : 0.0f;
                om[p] = rintf(val);   // round-half-even == jnp.round
            }
        }

        // last mask block of this batch resets the handshake state (replay determinism)
        __syncthreads();
        if (tid == 0) {
            __threadfence();
            int c = atomicAdd(&g_mdone[b], 1);
            if (c == TR - 1) {
                g_ready[b] = 0;
                g_mdone[b] = 0;
                __threadfence();
            }
        }
        return;
    }

    // =================== CLASSIFY BLOCKS ===================
    const int b   = blockIdx.x / CBLK_PER_B;
    const int blk = blockIdx.x % CBLK_PER_B;
    const int n   = blk * 256 + tid;

    __shared__ float         s_gt[NGT][4];
    __shared__ int           s_cls[NGT];
    __shared__ unsigned char s_fg[NGT], s_crowd[NGT];

    const float* P = props + (size_t)b * NPROP * 4;
    const float* G = gtb   + (size_t)b * NGT * 4;
    const int*   C = cls   + (size_t)b * NGT;

    if (tid < NGT) {
        float g0 = G[tid*4+0], g1 = G[tid*4+1], g2 = G[tid*4+2], g3 = G[tid*4+3];
        s_gt[tid][0] = g0; s_gt[tid][1] = g1; s_gt[tid][2] = g2; s_gt[tid][3] = g3;
        bool vg = (fabsf(g0)+fabsf(g1)+fabsf(g2)+fabsf(g3)) > 0.0f;
        int c = C[tid];
        s_cls[tid]   = c;
        s_fg[tid]    = (vg && c > 0) ? 1 : 0;
        s_crowd[tid] = (vg && c < 0) ? 1 : 0;
    }

    // dtype probe (block 0 only): 256 threads x 8 words = 2048 words
    if (blockIdx.x == 0) {
        const unsigned* maskw = (const unsigned*)masks;
        unsigned local = 0u;
        #pragma unroll
        for (int it = 0; it < 8; it++) {
            unsigned v = maskw[tid + it * 256];
            if (v == 0u || v == 1u) continue;                        // i32-compatible
            else if (v == 0x3F803F80u || v == 0x00003F80u) local |= 4u;  // bf16 pair
            else if (v == 0x3F800000u)                     local |= 2u;  // f32 1.0
            else if ((v & ~0x01010101u) == 0u)             local |= 1u;  // u8 bytes
        }
        local = __reduce_or_sync(0xffffffffu, local);
        if ((tid & 31) == 0 && local) atomicOr(&g_maskflags, local);
    }
    __syncthreads();

    // ---- classify one proposal per thread ----
    bool pb = false, nb = false;
    unsigned char asg = 0;
    if (n < NPROP) {
        float p0 = P[n*4+0], p1 = P[n*4+1], p2 = P[n*4+2], p3 = P[n*4+3];
        bool vp = (fabsf(p0)+fabsf(p1)+fabsf(p2)+fabsf(p3)) > 0.0f;
        float a1 = (p2 - p0) * (p3 - p1);
        float fgmax = 0.0f, crmax = 0.0f, best = -1e30f;
        int bi = 0;
        #pragma unroll 4
        for (int g = 0; g < NGT; g++) {
            float q0 = s_gt[g][0], q1 = s_gt[g][1], q2 = s_gt[g][2], q3 = s_gt[g][3];
            float y1 = fmaxf(p0, q0);
            float x1 = fmaxf(p1, q1);
            float y2 = fminf(p2, q2);
            float x2 = fminf(p3, q3);
            float inter = fmaxf(x2 - x1, 0.0f) * fmaxf(y2 - y1, 0.0f);
            float a2 = (q2 - q0) * (q3 - q1);
            float un = a1 + a2 - inter;
            float iou = (un > 0.0f) ? (inter / un) : 0.0f;
            if (!vp) iou = 0.0f;
            if (s_crowd[g] && iou > crmax) crmax = iou;
            float fv = s_fg[g] ? iou : 0.0f;
            if (fv > fgmax) fgmax = fv;
            float av = s_fg[g] ? iou : -1.0f;
            if (av > best) { best = av; bi = g; }
        }
        pb = (fgmax >= 0.5f) && vp;
        nb = (fgmax <  0.5f) && (crmax < 0.001f) && vp;
        asg = (unsigned char)bi;
    }
    unsigned pm = __ballot_sync(0xffffffffu, pb);
    unsigned nm = __ballot_sync(0xffffffffu, nb);
    const int w = n >> 5;
    if ((tid & 31) == 0) { g_pb[b][w] = pm; g_nb[b][w] = nm; }
    g_asg[b][n] = asg;

    // ---- last classify block per batch finalizes ----
    __shared__ int s_isLast;
    __syncthreads();
    if (tid == 0) {
        __threadfence();
        int old = atomicAdd(&g_done[b], 1);
        s_isLast = (old == CBLK_PER_B - 1) ? 1 : 0;
    }
    __syncthreads();
    if (!s_isLast) return;
    __threadfence();

    __shared__ unsigned s_pw[64], s_nw[64];
    __shared__ int      s_pbase[64], s_nbase[64];
    __shared__ int      s_pord[PM];
    __shared__ int      s_nord[TR];
    __shared__ int      s_Np, s_Nn;

    if (tid < 63) { s_pw[tid] = g_pb[b][tid]; s_nw[tid] = g_nb[b][tid]; }
    __syncthreads();

    if (tid == 0) {
        int rp = 0, rn = 0;
        for (int v = 0; v < 63; v++) {
            s_pbase[v] = rp; rp += __popc(s_pw[v]);
            s_nbase[v] = rn; rn += __popc(s_nw[v]);
        }
        int Np = min(rp, PM);
        const float R = (float)(1.0 / 0.33);
        int want = (int)floorf(R * (float)Np) - Np;
        int Nn = min(want, rn);
        Nn = max(Nn, 0);
        Nn = min(Nn, TR - Np);
        s_Np = Np; s_Nn = Nn;
        g_done[b] = 0;                    // reset for next graph replay
    }
    __syncthreads();

    if (tid < 63) {
        unsigned pw = s_pw[tid], nw = s_nw[tid];
        int base = s_pbase[tid];
        while (pw) {
            int l = __ffs(pw) - 1; pw &= pw - 1;
            if (base < PM) s_pord[base] = (tid << 5) + l;
            base++;
        }
        base = s_nbase[tid];
        while (nw) {
            int l = __ffs(nw) - 1; nw &= nw - 1;
            if (base < TR) s_nord[base] = (tid << 5) + l;
            base++;
        }
    }
    __syncthreads();

    const int Np = s_Np, Nn = s_Nn;
    if (tid < TR) {
        const int j = tid;
        float* ro = out + (size_t)(b * TR + j) * 4;
        float* cl = out + 1600 + (size_t)(b * TR + j);
        float* de = out + 2000 + (size_t)(b * TR + j) * 4;
        if (j < Np) {
            int nn = s_pord[j];
            int g  = g_asg[b][nn];
            float p0 = P[nn*4+0], p1 = P[nn*4+1], p2 = P[nn*4+2], p3 = P[nn*4+3];
            ro[0] = p0; ro[1] = p1; ro[2] = p2; ro[3] = p3;
            cl[0] = (float)s_cls[g];
            float h  = p2 - p0, w2 = p3 - p1;
            float cy = p0 + 0.5f * h, cx = p1 + 0.5f * w2;
            float g0 = s_gt[g][0], g1 = s_gt[g][1], g2 = s_gt[g][2], g3 = s_gt[g][3];
            float gh = g2 - g0, gw = g3 - g1;
            float gcy = g0 + 0.5f * gh, gcx = g1 + 0.5f * gw;
            de[0] = ((gcy - cy) / h)  / 0.1f;
            de[1] = ((gcx - cx) / w2) / 0.1f;
            de[2] = logf(gh / h)  / 0.2f;
            de[3] = logf(gw / w2) / 0.2f;
            if (j < PM) { g_posidx[b * PM + j] = nn; g_posg[b * PM + j] = g; }
        } else if (j < Np + Nn) {
            int nn = s_nord[j - Np];
            ro[0] = P[nn*4+0]; ro[1] = P[nn*4+1]; ro[2] = P[nn*4+2]; ro[3] = P[nn*4+3];
            cl[0] = 0.0f;
            de[0] = de[1] = de[2] = de[3] = 0.0f;
        } else {
            ro[0] = ro[1] = ro[2] = ro[3] = 0.0f;
            cl[0] = 0.0f;
            de[0] = de[1] = de[2] = de[3] = 0.0f;
        }
    }
    __syncthreads();

    // release the mask blocks for this batch
    if (tid == 0) {
        if (s_Np >= 0) {             // always true; keeps ordering obvious
            *((volatile int*)&g_npos[b]) = s_Np;
            __threadfence();
            atomicExch(&g_ready[b], 1);
        }
    }
}

// ---------------------------------------------------------------------------
extern "C" void kernel_launch(void* const* d_in, const int* in_sizes, int n_in,
                              void* d_out, int out_size)
{
    const float* props = (const float*)d_in[0];
    const int*   cls   = (const int*)  d_in[1];
    const float* gtb   = (const float*)d_in[2];
    const void*  masks = d_in[3];
    float* out = (float*)d_out;

    dtl_fused<<<NCBLK + NMBLK, 256>>>(props, cls, gtb, masks, out);
}

// round 4
// speedup vs baseline: 4.0572x; 1.7229x over previous
#include <cuda_runtime.h>
#include <cuda_bf16.h>
#include <math.h>

#define NPROP 2000
#define NGT   100
#define TR    200
#define PM    66      // POS_MAX = int(200*0.33)
#define HH    512
#define WW    512
#define MS    28
#define WPB   8                       // warps per classify block
#define CBLK_PER_B (NPROP / WPB)      // 250
#define NCBLK (2 * CBLK_PER_B)        // 500
#define NMBLK (2 * TR)                // 400

// inter-block state (no allocs allowed -> device globals)
__device__ int      g_npos[2];
__device__ int      g_posidx[2 * PM];
__device__ int      g_posg[2 * PM];
__device__ unsigned g_maskflags;        // OR-accumulated: idempotent across replays
__device__ unsigned g_info[2][2048];    // per-proposal: asg<<2 | pb<<1 | nb (overwrite)
__device__ int      g_done[2];          // classify-done counter (reset by finalizer)
__device__ int      g_ready[2];         // set by finalizer, reset by last mask block
__device__ int      g_mdone[2];         // mask-done counter (reset by last mask block)

__device__ __forceinline__ float cvtf(float v)          { return v; }
__device__ __forceinline__ float cvtf(int v)            { return (float)v; }
__device__ __forceinline__ float cvtf(unsigned char v)  { return (float)v; }
__device__ __forceinline__ float cvtf(__nv_bfloat16 v)  { return __bfloat162float(v); }

// Batched 28x28 bilinear gather: 4 pixel slots/thread, all 16 loads issued
// before any combine (MLP=16).
template <typename T>
__device__ __forceinline__ void do_gather(
    const T* __restrict__ m, float* __restrict__ om,
    float y1, float x1, float sy, float sx, unsigned mb, int g, int tid)
{
    unsigned idx[4][4];
    float    wyv[4], wxv[4];
    bool     okv[4], act[4];
    #pragma unroll
    for (int s = 0; s < 4; s++) {
        int p = tid + s * 256;
        act[s] = (p < MS * MS);
        int pc = act[s] ? p : 0;
        int i = pc / MS, k = pc - i * MS;
        float ys = y1 * 511.0f + (float)i * sy;
        float xs = x1 * 511.0f + (float)k * sx;
        float y0f = floorf(ys), x0f = floorf(xs);
        wyv[s] = ys - y0f; wxv[s] = xs - x0f;
        int y0i = (int)fminf(fmaxf(y0f,        0.0f), 511.0f);
        int y1i = (int)fminf(fmaxf(y0f + 1.0f, 0.0f), 511.0f);
        int x0i = (int)fminf(fmaxf(x0f,        0.0f), 511.0f);
        int x1i = (int)fminf(fmaxf(x0f + 1.0f, 0.0f), 511.0f);
        idx[s][0] = mb + (unsigned)(y0i * WW + x0i) * NGT + g;
        idx[s][1] = mb + (unsigned)(y0i * WW + x1i) * NGT + g;
        idx[s][2] = mb + (unsigned)(y1i * WW + x0i) * NGT + g;
        idx[s][3] = mb + (unsigned)(y1i * WW + x1i) * NGT + g;
        okv[s] = (ys >= 0.0f) && (ys <= 511.0f) && (xs >= 0.0f) && (xs <= 511.0f);
    }
    float v[4][4];
    #pragma unroll
    for (int s = 0; s < 4; s++)
        #pragma unroll
        for (int q = 0; q < 4; q++)
            v[s][q] = cvtf(m[idx[s][q]]);
    #pragma unroll
    for (int s = 0; s < 4; s++) {
        if (!act[s]) continue;
        float val = (v[s][0] * (1.0f - wxv[s]) + v[s][1] * wxv[s]) * (1.0f - wyv[s])
                  + (v[s][2] * (1.0f - wxv[s]) + v[s][3] * wxv[s]) * wyv[s];
        om[tid + s * 256] = okv[s] ? rintf(val) : 0.0f;   // half-even == jnp.round
    }
}

// ---------------------------------------------------------------------------
// Fused kernel.
//  blocks [0, NCBLK): warp-per-proposal classify + per-batch finalize
//  blocks [NCBLK, NCBLK+NMBLK): one ROI row each; zero, spin, gather
// ---------------------------------------------------------------------------
__global__ __launch_bounds__(256) void dtl_fused(
    const float* __restrict__ props,
    const int*   __restrict__ cls,
    const float* __restrict__ gtb,
    const void*  __restrict__ masks,
    float*       __restrict__ out)
{
    const int tid = threadIdx.x;

    // =================== MASK BLOCKS ===================
    if (blockIdx.x >= NCBLK) {
        const int bj = blockIdx.x - NCBLK;
        const int b = bj / TR, j = bj % TR;
        float* om = out + 3600 + (size_t)(b * TR + j) * (MS * MS);

        // eager zero (overlaps with classification)
        #pragma unroll
        for (int p = tid; p < MS * MS; p += 256) om[p] = 0.0f;

        // wait for classification of this batch
        __shared__ int s_go;
        if (tid == 0) {
            while (*((volatile int*)&g_ready[b]) == 0) __nanosleep(64);
            __threadfence();
            s_go = 1;
        }
        __syncthreads();
        (void)s_go;

        const int Np = *((volatile int*)&g_npos[b]);
        if (j < Np) {
            const int n = g_posidx[b * PM + j];
            const int g = g_posg[b * PM + j];
            const float* P = props + ((size_t)b * NPROP + n) * 4;
            const float y1 = P[0], x1 = P[1], y2 = P[2], x2 = P[3];
            const float sy = ((y2 - y1) * 511.0f) / 27.0f;
            const float sx = ((x2 - x1) * 511.0f) / 27.0f;
            const unsigned mode = g_maskflags;
            const unsigned mb = (unsigned)b * (HH * WW * NGT);
            if      (mode & 4u) do_gather((const __nv_bfloat16*)masks, om, y1, x1, sy, sx, mb, g, tid);
            else if (mode & 2u) do_gather((const float*)masks,          om, y1, x1, sy, sx, mb, g, tid);
            else if (mode & 1u) do_gather((const unsigned char*)masks,  om, y1, x1, sy, sx, mb, g, tid);
            else                do_gather((const int*)masks,            om, y1, x1, sy, sx, mb, g, tid);
        }

        // every mask block participates in the handshake reset (replay determinism)
        __syncthreads();
        if (tid == 0) {
            __threadfence();
            int c = atomicAdd(&g_mdone[b], 1);
            if (c == TR - 1) {
                g_ready[b] = 0;
                g_mdone[b] = 0;
                __threadfence();
            }
        }
        return;
    }

    // =================== CLASSIFY BLOCKS ===================
    const int b   = blockIdx.x / CBLK_PER_B;
    const int blk = blockIdx.x % CBLK_PER_B;
    const int wid  = tid >> 5;
    const int lane = tid & 31;
    const int n    = blk * WPB + wid;         // proposal handled by this warp

    __shared__ float         s_gt[NGT][5];    // pad: conflict-free lane-strided reads
    __shared__ int           s_cls[NGT];
    __shared__ unsigned char s_fg[NGT], s_crowd[NGT];

    const float* P = props + (size_t)b * NPROP * 4;
    const float* G = gtb   + (size_t)b * NGT * 4;
    const int*   C = cls   + (size_t)b * NGT;

    if (tid < NGT) {
        float g0 = G[tid*4+0], g1 = G[tid*4+1], g2 = G[tid*4+2], g3 = G[tid*4+3];
        s_gt[tid][0] = g0; s_gt[tid][1] = g1; s_gt[tid][2] = g2; s_gt[tid][3] = g3;
        bool vg = (fabsf(g0)+fabsf(g1)+fabsf(g2)+fabsf(g3)) > 0.0f;
        int c = C[tid];
        s_cls[tid]   = c;
        s_fg[tid]    = (vg && c > 0) ? 1 : 0;
        s_crowd[tid] = (vg && c < 0) ? 1 : 0;
    }

    // dtype probe (block 0 only): 256 threads x 8 words = 2048 words, idempotent
    if (blockIdx.x == 0) {
        const unsigned* maskw = (const unsigned*)masks;
        unsigned local = 0u;
        #pragma unroll
        for (int it = 0; it < 8; it++) {
            unsigned v = maskw[tid + it * 256];
            if (v == 0u || v == 1u) continue;                        // i32-compatible
            else if (v == 0x3F803F80u || v == 0x00003F80u) local |= 4u;  // bf16 pair
            else if (v == 0x3F800000u)                     local |= 2u;  // f32 1.0
            else if ((v & ~0x01010101u) == 0u)             local |= 1u;  // u8 bytes
        }
        local = __reduce_or_sync(0xffffffffu, local);
        if ((tid & 31) == 0 && local) atomicOr(&g_maskflags, local);
    }
    __syncthreads();

    // ---- classify: one proposal per WARP, lanes split the 100 GTs ----
    {
        const float4 pv = ((const float4*)P)[n];        // broadcast within warp
        const float p0 = pv.x, p1 = pv.y, p2 = pv.z, p3 = pv.w;
        const bool vp = (fabsf(p0)+fabsf(p1)+fabsf(p2)+fabsf(p3)) > 0.0f;
        const float a1 = (p2 - p0) * (p3 - p1);
        float fgmax = 0.0f, crmax = 0.0f, best = -1e30f;
        int bi = 0;
        #pragma unroll
        for (int t = 0; t < 4; t++) {
            int g = lane + t * 32;
            if (g < NGT) {
                float q0 = s_gt[g][0], q1 = s_gt[g][1], q2 = s_gt[g][2], q3 = s_gt[g][3];
                float y1 = fmaxf(p0, q0);
                float x1 = fmaxf(p1, q1);
                float y2 = fminf(p2, q2);
                float x2 = fminf(p3, q3);
                float inter = fmaxf(x2 - x1, 0.0f) * fmaxf(y2 - y1, 0.0f);
                float a2 = (q2 - q0) * (q3 - q1);
                float un = a1 + a2 - inter;
                float iou = (un > 0.0f) ? (inter / un) : 0.0f;
                if (!vp) iou = 0.0f;
                if (s_crowd[g] && iou > crmax) crmax = iou;
                float fv = s_fg[g] ? iou : 0.0f;
                if (fv > fgmax) fgmax = fv;
                float av = s_fg[g] ? iou : -1.0f;
                if (av > best) { best = av; bi = g; }   // ascending g: keeps first max
            }
        }
        // warp reductions (argmax: min-index tie-break == jnp.argmax)
        #pragma unroll
        for (int off = 16; off; off >>= 1) {
            fgmax = fmaxf(fgmax, __shfl_xor_sync(0xffffffffu, fgmax, off));
            crmax = fmaxf(crmax, __shfl_xor_sync(0xffffffffu, crmax, off));
            float ob = __shfl_xor_sync(0xffffffffu, best, off);
            int   og = __shfl_xor_sync(0xffffffffu, bi,   off);
            if (ob > best || (ob == best && og < bi)) { best = ob; bi = og; }
        }
        if (lane == 0) {
            unsigned pb = ((fgmax >= 0.5f) && vp) ? 1u : 0u;
            unsigned nb = ((fgmax <  0.5f) && (crmax < 0.001f) && vp) ? 1u : 0u;
            g_info[b][n] = ((unsigned)bi << 2) | (pb << 1) | nb;
        }
    }
    __threadfence();          // publish g_info (all threads; writers included)
    __syncthreads();

    // ---- last classify block per batch finalizes ----
    __shared__ int s_isLast;
    if (tid == 0) {
        int old = atomicAdd(&g_done[b], 1);
        s_isLast = (old == CBLK_PER_B - 1) ? 1 : 0;
    }
    __syncthreads();
    if (!s_isLast) return;
    __threadfence();          // acquire: see all blocks' g_info

    __shared__ unsigned s_pw[64], s_nw[64];
    __shared__ int      s_pbase[64], s_nbase[64];
    __shared__ int      s_pord[PM];
    __shared__ int      s_nord[TR];
    __shared__ int      s_Np, s_Nn;
    __shared__ unsigned s_info[2048];

    // rebuild bitmasks by ballot over g_info (indices >=2000 are always 0)
    #pragma unroll
    for (int it = 0; it < 8; it++) {
        int m = it * 256 + tid;
        unsigned info = g_info[b][m];
        s_info[m] = info;
        unsigned pmask = __ballot_sync(0xffffffffu, info & 2u);
        unsigned nmask = __ballot_sync(0xffffffffu, info & 1u);
        if ((tid & 31) == 0) {
            s_pw[it * 8 + (tid >> 5)] = pmask;
            s_nw[it * 8 + (tid >> 5)] = nmask;
        }
    }
    __syncthreads();

    if (tid == 0) {
        int rp = 0, rn = 0;
        for (int v = 0; v < 64; v++) {
            s_pbase[v] = rp; rp += __popc(s_pw[v]);
            s_nbase[v] = rn; rn += __popc(s_nw[v]);
        }
        int Np = min(rp, PM);
        const float R = (float)(1.0 / 0.33);
        int want = (int)floorf(R * (float)Np) - Np;
        int Nn = min(want, rn);
        Nn = max(Nn, 0);
        Nn = min(Nn, TR - Np);
        s_Np = Np; s_Nn = Nn;
        g_done[b] = 0;                    // reset for next graph replay
    }
    __syncthreads();

    if (tid < 64) {
        unsigned pw = s_pw[tid], nw = s_nw[tid];
        int base = s_pbase[tid];
        while (pw) {
            int l = __ffs(pw) - 1; pw &= pw - 1;
            if (base < PM) s_pord[base] = (tid << 5) + l;
            base++;
        }
        base = s_nbase[tid];
        while (nw) {
            int l = __ffs(nw) - 1; nw &= nw - 1;
            if (base < TR) s_nord[base] = (tid << 5) + l;
            base++;
        }
    }
    __syncthreads();

    const int Np = s_Np, Nn = s_Nn;

    // publish mask-phase inputs FIRST, then release the mask blocks
    if (tid < PM && tid < Np) {
        int nn = s_pord[tid];
        g_posidx[b * PM + tid] = nn;
        g_posg[b * PM + tid]   = (int)(s_info[nn] >> 2);
    }
    __threadfence();
    __syncthreads();
    if (tid == 0) {
        *((volatile int*)&g_npos[b]) = Np;
        __threadfence();
        atomicExch(&g_ready[b], 1);
    }

    // epilogue: rois / class_ids / deltas (overlaps with mask gathers)
    if (tid < TR) {
        const int j = tid;
        float* ro = out + (size_t)(b * TR + j) * 4;
        float* cl = out + 1600 + (size_t)(b * TR + j);
        float* de = out + 2000 + (size_t)(b * TR + j) * 4;
        if (j < Np) {
            int nn = s_pord[j];
            int g  = (int)(s_info[nn] >> 2);
            float p0 = P[nn*4+0], p1 = P[nn*4+1], p2 = P[nn*4+2], p3 = P[nn*4+3];
            ro[0] = p0; ro[1] = p1; ro[2] = p2; ro[3] = p3;
            cl[0] = (float)s_cls[g];
            float h  = p2 - p0, w2 = p3 - p1;
            float cy = p0 + 0.5f * h, cx = p1 + 0.5f * w2;
            float g0 = s_gt[g][0], g1 = s_gt[g][1], g2 = s_gt[g][2], g3 = s_gt[g][3];
            float gh = g2 - g0, gw = g3 - g1;
            float gcy = g0 + 0.5f * gh, gcx = g1 + 0.5f * gw;
            de[0] = ((gcy - cy) / h)  / 0.1f;
            de[1] = ((gcx - cx) / w2) / 0.1f;
            de[2] = logf(gh / h)  / 0.2f;
            de[3] = logf(gw / w2) / 0.2f;
        } else if (j < Np + Nn) {
            int nn = s_nord[j - Np];
            ro[0] = P[nn*4+0]; ro[1] = P[nn*4+1]; ro[2] = P[nn*4+2]; ro[3] = P[nn*4+3];
            cl[0] = 0.0f;
            de[0] = de[1] = de[2] = de[3] = 0.0f;
        } else {
            ro[0] = ro[1] = ro[2] = ro[3] = 0.0f;
            cl[0] = 0.0f;
            de[0] = de[1] = de[2] = de[3] = 0.0f;
        }
    }
}

// ---------------------------------------------------------------------------
extern "C" void kernel_launch(void* const* d_in, const int* in_sizes, int n_in,
                              void* d_out, int out_size)
{
    const float* props = (const float*)d_in[0];
    const int*   cls   = (const int*)  d_in[1];
    const float* gtb   = (const float*)d_in[2];
    const void*  masks = d_in[3];
    float* out = (float*)d_out;

    dtl_fused<<<NCBLK + NMBLK, 256>>>(props, cls, gtb, masks, out);
}

// round 5
// speedup vs baseline: 4.2180x; 1.0396x over previous
#include <cuda_runtime.h>
#include <cuda_bf16.h>
#include <math.h>

#define NPROP 2000
#define NGT   100
#define TR    200
#define PM    66      // POS_MAX = int(200*0.33)
#define HH    512
#define WW    512
#define MS    28
#define WPB   8                       // warps per classify block
#define CBLK_PER_B (NPROP / WPB)      // 250
#define NCBLK (2 * CBLK_PER_B)        // 500 (total grid)
#define NMBLK (2 * TR)                // 400 blocks also carry a mask row

// inter-block state (no allocs allowed -> device globals)
__device__ int      g_npos[2];
__device__ int      g_posidx[2 * PM];
__device__ int      g_posg[2 * PM];
__device__ unsigned g_maskflags;        // OR-accumulated: idempotent across replays
__device__ unsigned g_info[2][2048];    // per-proposal: asg<<2 | pb<<1 | nb (overwrite)
__device__ int      g_done[2];          // classify-done counter (reset by finalizer)
__device__ int      g_ready[2];         // set by finalizer, reset by last mask block
__device__ int      g_mdone[2];         // mask-done counter (reset by last mask block)

__device__ __forceinline__ float cvtf(float v)          { return v; }
__device__ __forceinline__ float cvtf(int v)            { return (float)v; }
__device__ __forceinline__ float cvtf(unsigned char v)  { return (float)v; }
__device__ __forceinline__ float cvtf(__nv_bfloat16 v)  { return __bfloat162float(v); }

// Batched 28x28 bilinear gather: 4 pixel slots/thread, all 16 loads issued
// before any combine (MLP=16).
template <typename T>
__device__ __forceinline__ void do_gather(
    const T* __restrict__ m, float* __restrict__ om,
    float y1, float x1, float sy, float sx, unsigned mb, int g, int tid)
{
    unsigned idx[4][4];
    float    wyv[4], wxv[4];
    bool     okv[4], act[4];
    #pragma unroll
    for (int s = 0; s < 4; s++) {
        int p = tid + s * 256;
        act[s] = (p < MS * MS);
        int pc = act[s] ? p : 0;
        int i = pc / MS, k = pc - i * MS;
        float ys = y1 * 511.0f + (float)i * sy;
        float xs = x1 * 511.0f + (float)k * sx;
        float y0f = floorf(ys), x0f = floorf(xs);
        wyv[s] = ys - y0f; wxv[s] = xs - x0f;
        int y0i = (int)fminf(fmaxf(y0f,        0.0f), 511.0f);
        int y1i = (int)fminf(fmaxf(y0f + 1.0f, 0.0f), 511.0f);
        int x0i = (int)fminf(fmaxf(x0f,        0.0f), 511.0f);
        int x1i = (int)fminf(fmaxf(x0f + 1.0f, 0.0f), 511.0f);
        idx[s][0] = mb + (unsigned)(y0i * WW + x0i) * NGT + g;
        idx[s][1] = mb + (unsigned)(y0i * WW + x1i) * NGT + g;
        idx[s][2] = mb + (unsigned)(y1i * WW + x0i) * NGT + g;
        idx[s][3] = mb + (unsigned)(y1i * WW + x1i) * NGT + g;
        okv[s] = (ys >= 0.0f) && (ys <= 511.0f) && (xs >= 0.0f) && (xs <= 511.0f);
    }
    float v[4][4];
    #pragma unroll
    for (int s = 0; s < 4; s++)
        #pragma unroll
        for (int q = 0; q < 4; q++)
            v[s][q] = cvtf(m[idx[s][q]]);
    #pragma unroll
    for (int s = 0; s < 4; s++) {
        if (!act[s]) continue;
        float val = (v[s][0] * (1.0f - wxv[s]) + v[s][1] * wxv[s]) * (1.0f - wyv[s])
                  + (v[s][2] * (1.0f - wxv[s]) + v[s][3] * wxv[s]) * wyv[s];
        om[tid + s * 256] = okv[s] ? rintf(val) : 0.0f;   // half-even == jnp.round
    }
}

// ---------------------------------------------------------------------------
// Single-grid fused kernel (500 blocks x 256):
//   phase 1 (all blocks): warp-per-proposal classify; last block per batch
//                         finalizes, publishes, releases, writes epilogue.
//   phase 2 (blocks 0..399): one ROI mask row each.
// All 500 blocks are co-resident (8/SM needed, 17 possible) -> spin is safe.
// ---------------------------------------------------------------------------
__global__ __launch_bounds__(256) void dtl_fused(
    const float* __restrict__ props,
    const int*   __restrict__ cls,
    const float* __restrict__ gtb,
    const void*  __restrict__ masks,
    float*       __restrict__ out)
{
    const int tid = threadIdx.x;

    // =================== PHASE 1: CLASSIFY ===================
    const int b   = blockIdx.x / CBLK_PER_B;
    const int blk = blockIdx.x % CBLK_PER_B;
    const int wid  = tid >> 5;
    const int lane = tid & 31;
    const int n    = blk * WPB + wid;         // proposal handled by this warp

    __shared__ float         s_gt[NGT][5];    // pad 5: conflict-free strided reads
    __shared__ int           s_cls[NGT];
    __shared__ unsigned char s_fg[NGT], s_crowd[NGT];

    const float* P = props + (size_t)b * NPROP * 4;
    const float* G = gtb   + (size_t)b * NGT * 4;
    const int*   C = cls   + (size_t)b * NGT;

    if (tid < NGT) {
        float g0 = G[tid*4+0], g1 = G[tid*4+1], g2 = G[tid*4+2], g3 = G[tid*4+3];
        s_gt[tid][0] = g0; s_gt[tid][1] = g1; s_gt[tid][2] = g2; s_gt[tid][3] = g3;
        bool vg = (fabsf(g0)+fabsf(g1)+fabsf(g2)+fabsf(g3)) > 0.0f;
        int c = C[tid];
        s_cls[tid]   = c;
        s_fg[tid]    = (vg && c > 0) ? 1 : 0;
        s_crowd[tid] = (vg && c < 0) ? 1 : 0;
    }

    // dtype probe (block 0 only): 2048 words, idempotent across replays
    if (blockIdx.x == 0) {
        const unsigned* maskw = (const unsigned*)masks;
        unsigned local = 0u;
        #pragma unroll
        for (int it = 0; it < 8; it++) {
            unsigned v = maskw[tid + it * 256];
            if (v == 0u || v == 1u) continue;                        // i32-compatible
            else if (v == 0x3F803F80u || v == 0x00003F80u) local |= 4u;  // bf16 pair
            else if (v == 0x3F800000u)                     local |= 2u;  // f32 1.0
            else if ((v & ~0x01010101u) == 0u)             local |= 1u;  // u8 bytes
        }
        local = __reduce_or_sync(0xffffffffu, local);
        if ((tid & 31) == 0 && local) atomicOr(&g_maskflags, local);
    }
    __syncthreads();

    // one proposal per WARP, lanes split the 100 GTs
    {
        const float4 pv = ((const float4*)P)[n];        // broadcast within warp
        const float p0 = pv.x, p1 = pv.y, p2 = pv.z, p3 = pv.w;
        const bool vp = (fabsf(p0)+fabsf(p1)+fabsf(p2)+fabsf(p3)) > 0.0f;
        const float a1 = (p2 - p0) * (p3 - p1);
        float fgmax = 0.0f, crmax = 0.0f, best = -1e30f;
        int bi = 0;
        #pragma unroll
        for (int t = 0; t < 4; t++) {
            int g = lane + t * 32;
            if (g < NGT) {
                float q0 = s_gt[g][0], q1 = s_gt[g][1], q2 = s_gt[g][2], q3 = s_gt[g][3];
                float y1 = fmaxf(p0, q0);
                float x1 = fmaxf(p1, q1);
                float y2 = fminf(p2, q2);
                float x2 = fminf(p3, q3);
                float inter = fmaxf(x2 - x1, 0.0f) * fmaxf(y2 - y1, 0.0f);
                float a2 = (q2 - q0) * (q3 - q1);
                float un = a1 + a2 - inter;
                float iou = (un > 0.0f) ? (inter / un) : 0.0f;
                if (!vp) iou = 0.0f;
                if (s_crowd[g] && iou > crmax) crmax = iou;
                float fv = s_fg[g] ? iou : 0.0f;
                if (fv > fgmax) fgmax = fv;
                float av = s_fg[g] ? iou : -1.0f;
                if (av > best) { best = av; bi = g; }   // ascending g: keeps first max
            }
        }
        // warp reductions (argmax: min-index tie-break == jnp.argmax)
        #pragma unroll
        for (int off = 16; off; off >>= 1) {
            fgmax = fmaxf(fgmax, __shfl_xor_sync(0xffffffffu, fgmax, off));
            crmax = fmaxf(crmax, __shfl_xor_sync(0xffffffffu, crmax, off));
            float ob = __shfl_xor_sync(0xffffffffu, best, off);
            int   og = __shfl_xor_sync(0xffffffffu, bi,   off);
            if (ob > best || (ob == best && og < bi)) { best = ob; bi = og; }
        }
        if (lane == 0) {
            unsigned pb = ((fgmax >= 0.5f) && vp) ? 1u : 0u;
            unsigned nb = ((fgmax <  0.5f) && (crmax < 0.001f) && vp) ? 1u : 0u;
            g_info[b][n] = ((unsigned)bi << 2) | (pb << 1) | nb;
        }
    }
    __threadfence();          // publish g_info
    __syncthreads();

    // last classify block per batch finalizes
    __shared__ int s_isLast;
    if (tid == 0) {
        int old = atomicAdd(&g_done[b], 1);
        s_isLast = (old == CBLK_PER_B - 1) ? 1 : 0;
    }
    __syncthreads();

    if (s_isLast) {
        __threadfence();          // acquire all blocks' g_info

        __shared__ unsigned s_pw[64], s_nw[64];
        __shared__ int      s_pbase[64], s_nbase[64];
        __shared__ int      s_pord[PM];
        __shared__ int      s_nord[TR];
        __shared__ int      s_Np, s_Nn;
        __shared__ unsigned s_info[2048];

        #pragma unroll
        for (int it = 0; it < 8; it++) {
            int m = it * 256 + tid;
            unsigned info = g_info[b][m];
            s_info[m] = info;
            unsigned pmask = __ballot_sync(0xffffffffu, info & 2u);
            unsigned nmask = __ballot_sync(0xffffffffu, info & 1u);
            if ((tid & 31) == 0) {
                s_pw[it * 8 + (tid >> 5)] = pmask;
                s_nw[it * 8 + (tid >> 5)] = nmask;
            }
        }
        __syncthreads();

        if (tid == 0) {
            int rp = 0, rn = 0;
            for (int v = 0; v < 64; v++) {
                s_pbase[v] = rp; rp += __popc(s_pw[v]);
                s_nbase[v] = rn; rn += __popc(s_nw[v]);
            }
            int Np = min(rp, PM);
            const float R = (float)(1.0 / 0.33);
            int want = (int)floorf(R * (float)Np) - Np;
            int Nn = min(want, rn);
            Nn = max(Nn, 0);
            Nn = min(Nn, TR - Np);
            s_Np = Np; s_Nn = Nn;
            g_done[b] = 0;                    // reset for next graph replay
        }
        __syncthreads();

        if (tid < 64) {
            unsigned pw = s_pw[tid], nw = s_nw[tid];
            int base = s_pbase[tid];
            while (pw) {
                int l = __ffs(pw) - 1; pw &= pw - 1;
                if (base < PM) s_pord[base] = (tid << 5) + l;
                base++;
            }
            base = s_nbase[tid];
            while (nw) {
                int l = __ffs(nw) - 1; nw &= nw - 1;
                if (base < TR) s_nord[base] = (tid << 5) + l;
                base++;
            }
        }
        __syncthreads();

        const int Np = s_Np, Nn = s_Nn;

        // publish mask-phase inputs FIRST, then release
        if (tid < PM && tid < Np) {
            int nn = s_pord[tid];
            g_posidx[b * PM + tid] = nn;
            g_posg[b * PM + tid]   = (int)(s_info[nn] >> 2);
        }
        __threadfence();
        __syncthreads();
        if (tid == 0) {
            *((volatile int*)&g_npos[b]) = Np;
            __threadfence();
            atomicExch(&g_ready[b], 1);
        }

        // epilogue: rois / class_ids / deltas (overlaps with mask gathers)
        if (tid < TR) {
            const int j = tid;
            float* ro = out + (size_t)(b * TR + j) * 4;
            float* cl = out + 1600 + (size_t)(b * TR + j);
            float* de = out + 2000 + (size_t)(b * TR + j) * 4;
            if (j < Np) {
                int nn = s_pord[j];
                int g  = (int)(s_info[nn] >> 2);
                float p0 = P[nn*4+0], p1 = P[nn*4+1], p2 = P[nn*4+2], p3 = P[nn*4+3];
                ro[0] = p0; ro[1] = p1; ro[2] = p2; ro[3] = p3;
                cl[0] = (float)s_cls[g];
                float h  = p2 - p0, w2 = p3 - p1;
                float cy = p0 + 0.5f * h, cx = p1 + 0.5f * w2;
                float g0 = s_gt[g][0], g1 = s_gt[g][1], g2 = s_gt[g][2], g3 = s_gt[g][3];
                float gh = g2 - g0, gw = g3 - g1;
                float gcy = g0 + 0.5f * gh, gcx = g1 + 0.5f * gw;
                de[0] = ((gcy - cy) / h)  / 0.1f;
                de[1] = ((gcx - cx) / w2) / 0.1f;
                de[2] = logf(gh / h)  / 0.2f;
                de[3] = logf(gw / w2) / 0.2f;
            } else if (j < Np + Nn) {
                int nn = s_nord[j - Np];
                ro[0] = P[nn*4+0]; ro[1] = P[nn*4+1]; ro[2] = P[nn*4+2]; ro[3] = P[nn*4+3];
                cl[0] = 0.0f;
                de[0] = de[1] = de[2] = de[3] = 0.0f;
            } else {
                ro[0] = ro[1] = ro[2] = ro[3] = 0.0f;
                cl[0] = 0.0f;
                de[0] = de[1] = de[2] = de[3] = 0.0f;
            }
        }
        __syncthreads();
    }

    // =================== PHASE 2: MASK ROWS ===================
    if (blockIdx.x < NMBLK) {
        const int bm = blockIdx.x / TR;
        const int j  = blockIdx.x % TR;
        float* om = out + 3600 + (size_t)(bm * TR + j) * (MS * MS);

        __shared__ int s_go;
        if (tid == 0) {
            while (*((volatile int*)&g_ready[bm]) == 0) __nanosleep(32);
            __threadfence();
            s_go = 1;
        }
        __syncthreads();
        (void)s_go;

        const int Np = *((volatile int*)&g_npos[bm]);
        if (j < Np) {
            const int nn = g_posidx[bm * PM + j];
            const int g  = g_posg[bm * PM + j];
            const float* Pm = props + ((size_t)bm * NPROP + nn) * 4;
            const float y1 = Pm[0], x1 = Pm[1], y2 = Pm[2], x2 = Pm[3];
            const float sy = ((y2 - y1) * 511.0f) / 27.0f;
            const float sx = ((x2 - x1) * 511.0f) / 27.0f;
            const unsigned mode = g_maskflags;
            const unsigned mb = (unsigned)bm * (HH * WW * NGT);
            if      (mode & 4u) do_gather((const __nv_bfloat16*)masks, om, y1, x1, sy, sx, mb, g, tid);
            else if (mode & 2u) do_gather((const float*)masks,          om, y1, x1, sy, sx, mb, g, tid);
            else if (mode & 1u) do_gather((const unsigned char*)masks,  om, y1, x1, sy, sx, mb, g, tid);
            else                do_gather((const int*)masks,            om, y1, x1, sy, sx, mb, g, tid);
        } else {
            // dead row: zeros only (no eager pre-zero of live rows)
            #pragma unroll
            for (int p = tid; p < MS * MS; p += 256) om[p] = 0.0f;
        }

        // handshake reset (replay determinism); all TR blocks per batch take part
        __syncthreads();
        if (tid == 0) {
            __threadfence();
            int c = atomicAdd(&g_mdone[bm], 1);
            if (c == TR - 1) {
                g_ready[bm] = 0;
                g_mdone[bm] = 0;
                __threadfence();
            }
        }
    }
}

// ---------------------------------------------------------------------------
extern "C" void kernel_launch(void* const* d_in, const int* in_sizes, int n_in,
                              void* d_out, int out_size)
{
    const float* props = (const float*)d_in[0];
    const int*   cls   = (const int*)  d_in[1];
    const float* gtb   = (const float*)d_in[2];
    const void*  masks = d_in[3];
    float* out = (float*)d_out;

    dtl_fused<<<NCBLK, 256>>>(props, cls, gtb, masks, out);
}

// round 6
// speedup vs baseline: 4.6117x; 1.0933x over previous
#include <cuda_runtime.h>
#include <cuda_bf16.h>
#include <math.h>

#define NPROP 2000
#define NGT   100
#define TR    200
#define PM    66      // POS_MAX = int(200*0.33)
#define HH    512
#define WW    512
#define MS    28
#define BT    512                 // threads per block
#define PWPB  10                  // busy classify warps per block (10 props/block)
#define BPB   200                 // blocks per batch (= TR, each also owns a mask row)
#define NBLK  (2 * BPB)           // 400

// inter-block state (no allocs allowed -> device globals)
__device__ int      g_npos[2];
__device__ int      g_posidx[2 * PM];
__device__ int      g_posg[2 * PM];
__device__ unsigned g_maskflags;        // OR-accumulated: idempotent across replays
__device__ unsigned g_info[2][2048];    // per-proposal: asg<<2 | pb<<1 | nb (overwrite)
__device__ int      g_done[2];          // classify-done counter (reset by finalizer)
__device__ int      g_ready[2];         // set by finalizer, reset by 200th waiter
__device__ int      g_mdone[2];         // wait-passed counter (reset by 200th waiter)

__device__ __forceinline__ float cvtf(float v)          { return v; }
__device__ __forceinline__ float cvtf(int v)            { return (float)v; }
__device__ __forceinline__ float cvtf(unsigned char v)  { return (float)v; }
__device__ __forceinline__ float cvtf(__nv_bfloat16 v)  { return __bfloat162float(v); }

// Batched 28x28 bilinear gather: 2 pixel slots/thread (512 thr), all 8 loads
// issued before any combine.
template <typename T>
__device__ __forceinline__ void do_gather(
    const T* __restrict__ m, float* __restrict__ om,
    float y1, float x1, float sy, float sx, unsigned mb, int g, int tid)
{
    unsigned idx[2][4];
    float    wyv[2], wxv[2];
    bool     okv[2], act[2];
    #pragma unroll
    for (int s = 0; s < 2; s++) {
        int p = tid + s * BT;
        act[s] = (p < MS * MS);
        int pc = act[s] ? p : 0;
        int i = pc / MS, k = pc - i * MS;
        float ys = y1 * 511.0f + (float)i * sy;
        float xs = x1 * 511.0f + (float)k * sx;
        float y0f = floorf(ys), x0f = floorf(xs);
        wyv[s] = ys - y0f; wxv[s] = xs - x0f;
        int y0i = (int)fminf(fmaxf(y0f,        0.0f), 511.0f);
        int y1i = (int)fminf(fmaxf(y0f + 1.0f, 0.0f), 511.0f);
        int x0i = (int)fminf(fmaxf(x0f,        0.0f), 511.0f);
        int x1i = (int)fminf(fmaxf(x0f + 1.0f, 0.0f), 511.0f);
        idx[s][0] = mb + (unsigned)(y0i * WW + x0i) * NGT + g;
        idx[s][1] = mb + (unsigned)(y0i * WW + x1i) * NGT + g;
        idx[s][2] = mb + (unsigned)(y1i * WW + x0i) * NGT + g;
        idx[s][3] = mb + (unsigned)(y1i * WW + x1i) * NGT + g;
        okv[s] = (ys >= 0.0f) && (ys <= 511.0f) && (xs >= 0.0f) && (xs <= 511.0f);
    }
    float v[2][4];
    #pragma unroll
    for (int s = 0; s < 2; s++)
        #pragma unroll
        for (int q = 0; q < 4; q++)
            v[s][q] = cvtf(m[idx[s][q]]);
    #pragma unroll
    for (int s = 0; s < 2; s++) {
        if (!act[s]) continue;
        float val = (v[s][0] * (1.0f - wxv[s]) + v[s][1] * wxv[s]) * (1.0f - wyv[s])
                  + (v[s][2] * (1.0f - wxv[s]) + v[s][3] * wxv[s]) * wyv[s];
        om[tid + s * BT] = okv[s] ? rintf(val) : 0.0f;   // half-even == jnp.round
    }
}

// ---------------------------------------------------------------------------
// Single-grid fused kernel, 400 blocks x 512 (single wave, 3 blocks/SM):
//   phase 1: warp-per-proposal classify (10 warps/block); last block per
//            batch: pos scan -> publish -> RELEASE -> neg scan + epilogue.
//   phase 2: every block handles one ROI mask row; handshake reset happens
//            right after the wait (overlaps gathers, no serial tail).
// ---------------------------------------------------------------------------
__global__ __launch_bounds__(BT, 3) void dtl_fused(
    const float* __restrict__ props,
    const int*   __restrict__ cls,
    const float* __restrict__ gtb,
    const void*  __restrict__ masks,
    float*       __restrict__ out)
{
    const int tid = threadIdx.x;
    const int b   = blockIdx.x / BPB;        // batch
    const int k   = blockIdx.x % BPB;        // block-in-batch == mask row
    const int wid  = tid >> 5;
    const int lane = tid & 31;

    __shared__ float         s_gt[NGT][5];   // pad 5: conflict-free strided reads
    __shared__ int           s_cls[NGT];
    __shared__ unsigned char s_fg[NGT], s_crowd[NGT];

    const float* P = props + (size_t)b * NPROP * 4;
    const float* G = gtb   + (size_t)b * NGT * 4;
    const int*   C = cls   + (size_t)b * NGT;

    if (tid < NGT) {
        float g0 = G[tid*4+0], g1 = G[tid*4+1], g2 = G[tid*4+2], g3 = G[tid*4+3];
        s_gt[tid][0] = g0; s_gt[tid][1] = g1; s_gt[tid][2] = g2; s_gt[tid][3] = g3;
        bool vg = (fabsf(g0)+fabsf(g1)+fabsf(g2)+fabsf(g3)) > 0.0f;
        int c = C[tid];
        s_cls[tid]   = c;
        s_fg[tid]    = (vg && c > 0) ? 1 : 0;
        s_crowd[tid] = (vg && c < 0) ? 1 : 0;
    }

    // dtype probe (block 0 only): 2048 words, idempotent across replays
    if (blockIdx.x == 0) {
        const unsigned* maskw = (const unsigned*)masks;
        unsigned local = 0u;
        #pragma unroll
        for (int it = 0; it < 4; it++) {
            unsigned v = maskw[tid + it * BT];
            if (v == 0u || v == 1u) continue;                        // i32-compatible
            else if (v == 0x3F803F80u || v == 0x00003F80u) local |= 4u;  // bf16 pair
            else if (v == 0x3F800000u)                     local |= 2u;  // f32 1.0
            else if ((v & ~0x01010101u) == 0u)             local |= 1u;  // u8 bytes
        }
        local = __reduce_or_sync(0xffffffffu, local);
        if ((tid & 31) == 0 && local) atomicOr(&g_maskflags, local);
    }
    __syncthreads();

    // ---- classify: warps 0..9 each take one proposal, lanes split the GTs ----
    if (wid < PWPB) {
        const int n = k * PWPB + wid;
        const float4 pv = ((const float4*)P)[n];        // broadcast within warp
        const float p0 = pv.x, p1 = pv.y, p2 = pv.z, p3 = pv.w;
        const bool vp = (fabsf(p0)+fabsf(p1)+fabsf(p2)+fabsf(p3)) > 0.0f;
        const float a1 = (p2 - p0) * (p3 - p1);
        float fgmax = 0.0f, crmax = 0.0f, best = -1e30f;
        int bi = 0;
        #pragma unroll
        for (int t = 0; t < 4; t++) {
            int g = lane + t * 32;
            if (g < NGT) {
                float q0 = s_gt[g][0], q1 = s_gt[g][1], q2 = s_gt[g][2], q3 = s_gt[g][3];
                float y1 = fmaxf(p0, q0);
                float x1 = fmaxf(p1, q1);
                float y2 = fminf(p2, q2);
                float x2 = fminf(p3, q3);
                float inter = fmaxf(x2 - x1, 0.0f) * fmaxf(y2 - y1, 0.0f);
                float a2 = (q2 - q0) * (q3 - q1);
                float un = a1 + a2 - inter;
                float iou = (un > 0.0f) ? (inter / un) : 0.0f;
                if (!vp) iou = 0.0f;
                if (s_crowd[g] && iou > crmax) crmax = iou;
                float fv = s_fg[g] ? iou : 0.0f;
                if (fv > fgmax) fgmax = fv;
                float av = s_fg[g] ? iou : -1.0f;
                if (av > best) { best = av; bi = g; }   // ascending g: keeps first max
            }
        }
        #pragma unroll
        for (int off = 16; off; off >>= 1) {
            fgmax = fmaxf(fgmax, __shfl_xor_sync(0xffffffffu, fgmax, off));
            crmax = fmaxf(crmax, __shfl_xor_sync(0xffffffffu, crmax, off));
            float ob = __shfl_xor_sync(0xffffffffu, best, off);
            int   og = __shfl_xor_sync(0xffffffffu, bi,   off);
            if (ob > best || (ob == best && og < bi)) { best = ob; bi = og; }
        }
        if (lane == 0) {
            unsigned pb = ((fgmax >= 0.5f) && vp) ? 1u : 0u;
            unsigned nb = ((fgmax <  0.5f) && (crmax < 0.001f) && vp) ? 1u : 0u;
            g_info[b][n] = ((unsigned)bi << 2) | (pb << 1) | nb;
        }
    }
    __threadfence();
    __syncthreads();

    __shared__ int s_isLast;
    if (tid == 0) {
        int old = atomicAdd(&g_done[b], 1);
        s_isLast = (old == BPB - 1) ? 1 : 0;
    }
    __syncthreads();

    if (s_isLast) {
        __threadfence();          // acquire all blocks' g_info

        __shared__ unsigned s_pw[64], s_nw[64];
        __shared__ int      s_pbase[64], s_nbase[64];
        __shared__ int      s_pord[PM];
        __shared__ int      s_nord[TR];
        __shared__ int      s_Np, s_Nn, s_rn;
        __shared__ unsigned s_info[2048];

        #pragma unroll
        for (int it = 0; it < 4; it++) {
            int m = it * BT + tid;
            unsigned info = g_info[b][m];
            s_info[m] = info;
            unsigned pmask = __ballot_sync(0xffffffffu, info & 2u);
            unsigned nmask = __ballot_sync(0xffffffffu, info & 1u);
            if ((tid & 31) == 0) {
                s_pw[it * 16 + (tid >> 5)] = pmask;
                s_nw[it * 16 + (tid >> 5)] = nmask;
            }
        }
        __syncthreads();

        // warp 0: exclusive scan of pos counts; warp 1: neg counts
        if (wid < 2) {
            unsigned* src = (wid == 0) ? s_pw : s_nw;
            int*      dst = (wid == 0) ? s_pbase : s_nbase;
            int a  = __popc(src[lane]);
            int b2 = __popc(src[lane + 32]);
            int ia = a, ib = b2;
            #pragma unroll
            for (int off = 1; off < 32; off <<= 1) {
                int t0 = __shfl_up_sync(0xffffffffu, ia, off);
                int t1 = __shfl_up_sync(0xffffffffu, ib, off);
                if (lane >= off) { ia += t0; ib += t1; }
            }
            int totA = __shfl_sync(0xffffffffu, ia, 31);
            dst[lane]      = ia - a;
            dst[lane + 32] = totA + ib - b2;
            if (lane == 31) {
                int tot = totA + ib;
                if (wid == 0) {
                    int Np = min(tot, PM);
                    s_Np = Np;
                    g_done[b] = 0;               // reset for next replay
                } else {
                    s_rn = tot;
                }
            }
        }
        __syncthreads();

        const int Np = s_Np;

        // pos compaction (critical path for mask release)
        if (tid < 64) {
            unsigned pw = s_pw[tid];
            int base = s_pbase[tid];
            while (pw) {
                int l = __ffs(pw) - 1; pw &= pw - 1;
                if (base < PM) s_pord[base] = (tid << 5) + l;
                base++;
            }
        }
        __syncthreads();

        // publish + neg compaction concurrently
        if (tid < PM && tid < Np) {
            int nn = s_pord[tid];
            g_posidx[b * PM + tid] = nn;
            g_posg[b * PM + tid]   = (int)(s_info[nn] >> 2);
        }
        if (tid >= 128 && tid < 192) {
            int v = tid - 128;
            unsigned nw = s_nw[v];
            int base = s_nbase[v];
            while (nw) {
                int l = __ffs(nw) - 1; nw &= nw - 1;
                if (base < TR) s_nord[base] = (v << 5) + l;
                base++;
            }
        }
        __threadfence();
        __syncthreads();

        // RELEASE (mask blocks start now; epilogue overlaps their gathers)
        if (tid == 0) {
            *((volatile int*)&g_npos[b]) = Np;
            __threadfence();
            atomicExch(&g_ready[b], 1);
            const float R = (float)(1.0 / 0.33);
            int want = (int)floorf(R * (float)Np) - Np;
            int Nn = min(want, s_rn);
            Nn = max(Nn, 0);
            s_Nn = min(Nn, TR - Np);
        }
        __syncthreads();
        const int Nn = s_Nn;

        // epilogue: rois / class_ids / deltas
        if (tid < TR) {
            const int j = tid;
            float* ro = out + (size_t)(b * TR + j) * 4;
            float* cl = out + 1600 + (size_t)(b * TR + j);
            float* de = out + 2000 + (size_t)(b * TR + j) * 4;
            if (j < Np) {
                int nn = s_pord[j];
                int g  = (int)(s_info[nn] >> 2);
                float p0 = P[nn*4+0], p1 = P[nn*4+1], p2 = P[nn*4+2], p3 = P[nn*4+3];
                ro[0] = p0; ro[1] = p1; ro[2] = p2; ro[3] = p3;
                cl[0] = (float)s_cls[g];
                float h  = p2 - p0, w2 = p3 - p1;
                float cy = p0 + 0.5f * h, cx = p1 + 0.5f * w2;
                float g0 = s_gt[g][0], g1 = s_gt[g][1], g2 = s_gt[g][2], g3 = s_gt[g][3];
                float gh = g2 - g0, gw = g3 - g1;
                float gcy = g0 + 0.5f * gh, gcx = g1 + 0.5f * gw;
                de[0] = ((gcy - cy) / h)  / 0.1f;
                de[1] = ((gcx - cx) / w2) / 0.1f;
                de[2] = logf(gh / h)  / 0.2f;
                de[3] = logf(gw / w2) / 0.2f;
            } else if (j < Np + Nn) {
                int nn = s_nord[j - Np];
                ro[0] = P[nn*4+0]; ro[1] = P[nn*4+1]; ro[2] = P[nn*4+2]; ro[3] = P[nn*4+3];
                cl[0] = 0.0f;
                de[0] = de[1] = de[2] = de[3] = 0.0f;
            } else {
                ro[0] = ro[1] = ro[2] = ro[3] = 0.0f;
                cl[0] = 0.0f;
                de[0] = de[1] = de[2] = de[3] = 0.0f;
            }
        }
    }

    // =================== PHASE 2: MASK ROW k ===================
    {
        const int j = k;
        float* om = out + 3600 + (size_t)(b * TR + j) * (MS * MS);

        __shared__ int s_go;
        if (tid == 0) {
            while (*((volatile int*)&g_ready[b]) == 0) __nanosleep(32);
            __threadfence();
            s_go = 1;
        }
        __syncthreads();
        (void)s_go;

        // handshake reset IMMEDIATELY after the wait passes -> the 200-atomic
        // chain overlaps the gathers instead of trailing them.
        if (tid == 0) {
            int c = atomicAdd(&g_mdone[b], 1);
            if (c == TR - 1) {
                g_ready[b] = 0;
                g_mdone[b] = 0;
                __threadfence();
            }
        }

        const int Np = *((volatile int*)&g_npos[b]);
        if (j < Np) {
            const int nn = g_posidx[b * PM + j];
            const int g  = g_posg[b * PM + j];
            const float* Pm = props + ((size_t)b * NPROP + nn) * 4;
            const float y1 = Pm[0], x1 = Pm[1], y2 = Pm[2], x2 = Pm[3];
            const float sy = ((y2 - y1) * 511.0f) / 27.0f;
            const float sx = ((x2 - x1) * 511.0f) / 27.0f;
            const unsigned mode = g_maskflags;
            const unsigned mb = (unsigned)b * (HH * WW * NGT);
            if      (mode & 4u) do_gather((const __nv_bfloat16*)masks, om, y1, x1, sy, sx, mb, g, tid);
            else if (mode & 2u) do_gather((const float*)masks,          om, y1, x1, sy, sx, mb, g, tid);
            else if (mode & 1u) do_gather((const unsigned char*)masks,  om, y1, x1, sy, sx, mb, g, tid);
            else                do_gather((const int*)masks,            om, y1, x1, sy, sx, mb, g, tid);
        } else {
            if (tid < MS * MS) om[tid] = 0.0f;
            int p2i = tid + BT;
            if (p2i < MS * MS) om[p2i] = 0.0f;
        }
    }
}

// ---------------------------------------------------------------------------
extern "C" void kernel_launch(void* const* d_in, const int* in_sizes, int n_in,
                              void* d_out, int out_size)
{
    const float* props = (const float*)d_in[0];
    const int*   cls   = (const int*)  d_in[1];
    const float* gtb   = (const float*)d_in[2];
    const void*  masks = d_in[3];
    float* out = (float*)d_out;

    dtl_fused<<<NBLK, BT>>>(props, cls, gtb, masks, out);
}

// round 7
// speedup vs baseline: 5.2405x; 1.1364x over previous
#include <cuda_runtime.h>
#include <cuda_bf16.h>
#include <math.h>

#define NPROP 2000
#define NGT   100
#define TR    200
#define PM    66      // POS_MAX = int(200*0.33)
#define HH    512
#define WW    512
#define MS    28
#define BT    512                 // threads per block
#define PWPB  10                  // proposals (classify warps) per block
#define BPB   200                 // blocks per batch (= TR; each owns one output row)
#define NBLK  (2 * BPB)           // 400

// inter-block state (no allocs allowed -> device globals; all overwrite-or-reset)
__device__ unsigned g_info[2][2048];      // per-proposal: asg<<2 | pb<<1 | nb
__device__ unsigned g_blockbits[2][BPB];  // per classify block: posbits | negbits<<10
__device__ int      g_done[2];            // classify-done counter (reset by 200th waiter)
__device__ int      g_mdone[2];           // wait-passed counter  (reset by 200th waiter)
__device__ unsigned g_maskflags;          // OR-accumulated dtype probe (idempotent)

__device__ __forceinline__ float cvtf(float v)          { return v; }
__device__ __forceinline__ float cvtf(int v)            { return (float)v; }
__device__ __forceinline__ float cvtf(unsigned char v)  { return (float)v; }
__device__ __forceinline__ float cvtf(__nv_bfloat16 v)  { return __bfloat162float(v); }

// Batched 28x28 bilinear gather: 2 pixel slots/thread (512 thr), all 8 loads
// issued before any combine.
template <typename T>
__device__ __forceinline__ void do_gather(
    const T* __restrict__ m, float* __restrict__ om,
    float y1, float x1, float sy, float sx, unsigned mb, int g, int tid)
{
    unsigned idx[2][4];
    float    wyv[2], wxv[2];
    bool     okv[2], act[2];
    #pragma unroll
    for (int s = 0; s < 2; s++) {
        int p = tid + s * BT;
        act[s] = (p < MS * MS);
        int pc = act[s] ? p : 0;
        int i = pc / MS, k = pc - i * MS;
        float ys = y1 * 511.0f + (float)i * sy;
        float xs = x1 * 511.0f + (float)k * sx;
        float y0f = floorf(ys), x0f = floorf(xs);
        wyv[s] = ys - y0f; wxv[s] = xs - x0f;
        int y0i = (int)fminf(fmaxf(y0f,        0.0f), 511.0f);
        int y1i = (int)fminf(fmaxf(y0f + 1.0f, 0.0f), 511.0f);
        int x0i = (int)fminf(fmaxf(x0f,        0.0f), 511.0f);
        int x1i = (int)fminf(fmaxf(x0f + 1.0f, 0.0f), 511.0f);
        idx[s][0] = mb + (unsigned)(y0i * WW + x0i) * NGT + g;
        idx[s][1] = mb + (unsigned)(y0i * WW + x1i) * NGT + g;
        idx[s][2] = mb + (unsigned)(y1i * WW + x0i) * NGT + g;
        idx[s][3] = mb + (unsigned)(y1i * WW + x1i) * NGT + g;
        okv[s] = (ys >= 0.0f) && (ys <= 511.0f) && (xs >= 0.0f) && (xs <= 511.0f);
    }
    float v[2][4];
    #pragma unroll
    for (int s = 0; s < 2; s++)
        #pragma unroll
        for (int q = 0; q < 4; q++)
            v[s][q] = cvtf(m[idx[s][q]]);
    #pragma unroll
    for (int s = 0; s < 2; s++) {
        if (!act[s]) continue;
        float val = (v[s][0] * (1.0f - wxv[s]) + v[s][1] * wxv[s]) * (1.0f - wyv[s])
                  + (v[s][2] * (1.0f - wxv[s]) + v[s][3] * wxv[s]) * wyv[s];
        om[tid + s * BT] = okv[s] ? rintf(val) : 0.0f;   // half-even == jnp.round
    }
}

// ---------------------------------------------------------------------------
// Fully decentralized fused kernel, 400 blocks x 512 (single wave, 3/SM):
//  1. each block classifies 10 proposals (warp-per-proposal), publishes a
//     20-bit summary word + per-proposal info, increments g_done[b].
//  2. each block spins until g_done[b]==BPB (reset overlapped via g_mdone).
//  3. each block SELF-FINALIZES: loads 200 summary words, scans -> Np/Nn,
//     binary-searches its own row's proposal, writes that row's rois/class/
//     deltas AND its 28x28 mask tile. No central finalizer, no release flag.
// ---------------------------------------------------------------------------
__global__ __launch_bounds__(BT, 3) void dtl_fused(
    const float* __restrict__ props,
    const int*   __restrict__ cls,
    const float* __restrict__ gtb,
    const void*  __restrict__ masks,
    float*       __restrict__ out)
{
    const int tid = threadIdx.x;
    const int b   = blockIdx.x / BPB;        // batch
    const int k   = blockIdx.x % BPB;        // block-in-batch == output row
    const int wid  = tid >> 5;
    const int lane = tid & 31;

    __shared__ float         s_gt[NGT][5];   // pad 5: conflict-free strided reads
    __shared__ int           s_cls[NGT];
    __shared__ unsigned char s_fg[NGT], s_crowd[NGT];
    __shared__ unsigned char s_p10[PWPB], s_n10[PWPB];

    const float* P = props + (size_t)b * NPROP * 4;
    const float* G = gtb   + (size_t)b * NGT * 4;
    const int*   C = cls   + (size_t)b * NGT;

    if (tid < NGT) {
        float g0 = G[tid*4+0], g1 = G[tid*4+1], g2 = G[tid*4+2], g3 = G[tid*4+3];
        s_gt[tid][0] = g0; s_gt[tid][1] = g1; s_gt[tid][2] = g2; s_gt[tid][3] = g3;
        bool vg = (fabsf(g0)+fabsf(g1)+fabsf(g2)+fabsf(g3)) > 0.0f;
        int c = C[tid];
        s_cls[tid]   = c;
        s_fg[tid]    = (vg && c > 0) ? 1 : 0;
        s_crowd[tid] = (vg && c < 0) ? 1 : 0;
    }

    // dtype probe (block 0 only): 2048 words, idempotent across replays
    if (blockIdx.x == 0) {
        const unsigned* maskw = (const unsigned*)masks;
        unsigned local = 0u;
        #pragma unroll
        for (int it = 0; it < 4; it++) {
            unsigned v = maskw[tid + it * BT];
            if (v == 0u || v == 1u) continue;                        // i32-compatible
            else if (v == 0x3F803F80u || v == 0x00003F80u) local |= 4u;  // bf16 pair
            else if (v == 0x3F800000u)                     local |= 2u;  // f32 1.0
            else if ((v & ~0x01010101u) == 0u)             local |= 1u;  // u8 bytes
        }
        local = __reduce_or_sync(0xffffffffu, local);
        if ((tid & 31) == 0 && local) atomicOr(&g_maskflags, local);
    }
    __syncthreads();

    // ---- classify: warps 0..9 each take one proposal, lanes split the GTs ----
    if (wid < PWPB) {
        const int n = k * PWPB + wid;
        const float4 pv = ((const float4*)P)[n];        // broadcast within warp
        const float p0 = pv.x, p1 = pv.y, p2 = pv.z, p3 = pv.w;
        const bool vp = (fabsf(p0)+fabsf(p1)+fabsf(p2)+fabsf(p3)) > 0.0f;
        const float a1 = (p2 - p0) * (p3 - p1);
        float fgmax = 0.0f, crmax = 0.0f, best = -1e30f;
        int bi = 0;
        #pragma unroll
        for (int t = 0; t < 4; t++) {
            int g = lane + t * 32;
            if (g < NGT) {
                float q0 = s_gt[g][0], q1 = s_gt[g][1], q2 = s_gt[g][2], q3 = s_gt[g][3];
                float y1 = fmaxf(p0, q0);
                float x1 = fmaxf(p1, q1);
                float y2 = fminf(p2, q2);
                float x2 = fminf(p3, q3);
                float inter = fmaxf(x2 - x1, 0.0f) * fmaxf(y2 - y1, 0.0f);
                float a2 = (q2 - q0) * (q3 - q1);
                float un = a1 + a2 - inter;
                float iou = (un > 0.0f) ? (inter / un) : 0.0f;
                if (!vp) iou = 0.0f;
                if (s_crowd[g] && iou > crmax) crmax = iou;
                float fv = s_fg[g] ? iou : 0.0f;
                if (fv > fgmax) fgmax = fv;
                float av = s_fg[g] ? iou : -1.0f;
                if (av > best) { best = av; bi = g; }   // ascending g: keeps first max
            }
        }
        #pragma unroll
        for (int off = 16; off; off >>= 1) {
            fgmax = fmaxf(fgmax, __shfl_xor_sync(0xffffffffu, fgmax, off));
            crmax = fmaxf(crmax, __shfl_xor_sync(0xffffffffu, crmax, off));
            float ob = __shfl_xor_sync(0xffffffffu, best, off);
            int   og = __shfl_xor_sync(0xffffffffu, bi,   off);
            if (ob > best || (ob == best && og < bi)) { best = ob; bi = og; }
        }
        if (lane == 0) {
            unsigned pb = ((fgmax >= 0.5f) && vp) ? 1u : 0u;
            unsigned nb = ((fgmax <  0.5f) && (crmax < 0.001f) && vp) ? 1u : 0u;
            g_info[b][n] = ((unsigned)bi << 2) | (pb << 1) | nb;
            s_p10[wid] = (unsigned char)pb;
            s_n10[wid] = (unsigned char)nb;
        }
    }
    __syncthreads();
    if (tid == 0) {
        unsigned w = 0u;
        #pragma unroll
        for (int i = 0; i < PWPB; i++)
            w |= ((unsigned)s_p10[i] << i) | ((unsigned)s_n10[i] << (10 + i));
        g_blockbits[b][k] = w;
    }
    __threadfence();
    __syncthreads();

    // ---- barrier: wait until all 200 classify blocks of this batch are done ----
    __shared__ int s_go;
    if (tid == 0) {
        atomicAdd(&g_done[b], 1);
        while (*((volatile int*)&g_done[b]) < BPB) __nanosleep(64);
        __threadfence();   // acquire
        s_go = 1;
    }
    __syncthreads();
    (void)s_go;

    // reset handshake overlapped with the work below (200th passer resets)
    if (tid == 0) {
        int c = atomicAdd(&g_mdone[b], 1);
        if (c == BPB - 1) {
            g_done[b]  = 0;
            g_mdone[b] = 0;
            __threadfence();
        }
    }

    // ---- self-finalize: scan 200 summary words ----
    __shared__ unsigned s_bits[224];
    __shared__ int s_cumP[224], s_cumN[224];
    __shared__ int s_wtP[8], s_wtN[8];
    __shared__ int s_Np, s_Nn, s_sel, s_selg;
    __shared__ float s_box[4];

    unsigned wbits = 0u; int pcnt = 0, ncnt = 0;
    if (tid < BPB) {
        wbits = g_blockbits[b][tid];
        pcnt = __popc(wbits & 0x3FFu);
        ncnt = __popc(wbits >> 10);
    }
    if (tid < 224) s_bits[tid] = wbits;
    int ip = pcnt, in_ = ncnt;
    if (wid < 7) {
        #pragma unroll
        for (int off = 1; off < 32; off <<= 1) {
            int a = __shfl_up_sync(0xffffffffu, ip,  off);
            int c = __shfl_up_sync(0xffffffffu, in_, off);
            if (lane >= off) { ip += a; in_ += c; }
        }
        if (lane == 31) { s_wtP[wid] = ip; s_wtN[wid] = in_; }
    }
    __syncthreads();
    if (tid == 0) {
        int rp = 0, rn = 0;
        #pragma unroll
        for (int i = 0; i < 7; i++) {
            int a = s_wtP[i], c = s_wtN[i];
            s_wtP[i] = rp; s_wtN[i] = rn;
            rp += a; rn += c;
        }
        int Np = min(rp, PM);
        const float R = (float)(1.0 / 0.33);
        int want = (int)floorf(R * (float)Np) - Np;
        int Nn = min(want, rn);
        Nn = max(Nn, 0);
        s_Np = Np;
        s_Nn = min(Nn, TR - Np);
    }
    __syncthreads();
    if (tid < BPB && wid < 7) {
        s_cumP[tid] = ip  + s_wtP[wid];
        s_cumN[tid] = in_ + s_wtN[wid];
    }
    __syncthreads();

    // locate this block's row (tid0), stash proposal box + assignment
    if (tid == 0) {
        const int Np = s_Np, Nn = s_Nn;
        int n = -1, g = 0;
        if (k < Np) {
            int lo = 0, hi = BPB - 1;
            while (lo < hi) { int mid = (lo + hi) >> 1; if (s_cumP[mid] > k) hi = mid; else lo = mid + 1; }
            int prev = lo ? s_cumP[lo - 1] : 0;
            int r = k - prev;
            unsigned pbits = s_bits[lo] & 0x3FFu;
            for (int i = 0; i < r; i++) pbits &= pbits - 1;
            n = lo * PWPB + (__ffs(pbits) - 1);
            g = (int)(g_info[b][n] >> 2);
        } else if (k < Np + Nn) {
            int j2 = k - Np;
            int lo = 0, hi = BPB - 1;
            while (lo < hi) { int mid = (lo + hi) >> 1; if (s_cumN[mid] > j2) hi = mid; else lo = mid + 1; }
            int prev = lo ? s_cumN[lo - 1] : 0;
            int r = j2 - prev;
            unsigned nbits = s_bits[lo] >> 10;
            for (int i = 0; i < r; i++) nbits &= nbits - 1;
            n = lo * PWPB + (__ffs(nbits) - 1);
        }
        s_sel = n; s_selg = g;
        if (n >= 0) {
            const float4 pv = ((const float4*)P)[n];
            s_box[0] = pv.x; s_box[1] = pv.y; s_box[2] = pv.z; s_box[3] = pv.w;
        }
    }
    __syncthreads();

    const int Np = s_Np, Nn = s_Nn, n = s_sel, g = s_selg;

    // row outputs: rois / class_ids / deltas (warp 1 lane 0, overlaps gather)
    if (tid == 32) {
        float* ro = out + (size_t)(b * TR + k) * 4;
        float* cl = out + 1600 + (size_t)(b * TR + k);
        float* de = out + 2000 + (size_t)(b * TR + k) * 4;
        if (k < Np) {
            float p0 = s_box[0], p1 = s_box[1], p2 = s_box[2], p3 = s_box[3];
            ro[0] = p0; ro[1] = p1; ro[2] = p2; ro[3] = p3;
            cl[0] = (float)s_cls[g];
            float h  = p2 - p0, w2 = p3 - p1;
            float cy = p0 + 0.5f * h, cx = p1 + 0.5f * w2;
            float g0 = s_gt[g][0], g1 = s_gt[g][1], g2 = s_gt[g][2], g3 = s_gt[g][3];
            float gh = g2 - g0, gw = g3 - g1;
            float gcy = g0 + 0.5f * gh, gcx = g1 + 0.5f * gw;
            de[0] = ((gcy - cy) / h)  / 0.1f;
            de[1] = ((gcx - cx) / w2) / 0.1f;
            de[2] = logf(gh / h)  / 0.2f;
            de[3] = logf(gw / w2) / 0.2f;
        } else if (k < Np + Nn) {
            ro[0] = s_box[0]; ro[1] = s_box[1]; ro[2] = s_box[2]; ro[3] = s_box[3];
            cl[0] = 0.0f;
            de[0] = de[1] = de[2] = de[3] = 0.0f;
        } else {
            ro[0] = ro[1] = ro[2] = ro[3] = 0.0f;
            cl[0] = 0.0f;
            de[0] = de[1] = de[2] = de[3] = 0.0f;
        }
    }

    // mask tile for row k
    {
        float* om = out + 3600 + (size_t)(b * TR + k) * (MS * MS);
        if (k < Np) {
            const float y1 = s_box[0], x1 = s_box[1], y2 = s_box[2], x2 = s_box[3];
            const float sy = ((y2 - y1) * 511.0f) / 27.0f;
            const float sx = ((x2 - x1) * 511.0f) / 27.0f;
            const unsigned mode = g_maskflags;
            const unsigned mb = (unsigned)b * (HH * WW * NGT);
            if      (mode & 4u) do_gather((const __nv_bfloat16*)masks, om, y1, x1, sy, sx, mb, g, tid);
            else if (mode & 2u) do_gather((const float*)masks,          om, y1, x1, sy, sx, mb, g, tid);
            else if (mode & 1u) do_gather((const unsigned char*)masks,  om, y1, x1, sy, sx, mb, g, tid);
            else                do_gather((const int*)masks,            om, y1, x1, sy, sx, mb, g, tid);
        } else {
            if (tid < MS * MS) om[tid] = 0.0f;
            int p2i = tid + BT;
            if (p2i < MS * MS) om[p2i] = 0.0f;
        }
    }
}

// ---------------------------------------------------------------------------
extern "C" void kernel_launch(void* const* d_in, const int* in_sizes, int n_in,
                              void* d_out, int out_size)
{
    const float* props = (const float*)d_in[0];
    const int*   cls   = (const int*)  d_in[1];
    const float* gtb   = (const float*)d_in[2];
    const void*  masks = d_in[3];
    float* out = (float*)d_out;

    dtl_fused<<<NBLK, BT>>>(props, cls, gtb, masks, out);
}